// round 14
// baseline (speedup 1.0000x reference)
#include <cuda_runtime.h>
#include <cuda_bf16.h>
#include <math.h>
#include <stdint.h>

#define S_     56
#define B_     32
#define C_     1024
#define T_     48
#define H_     1024
#define EMB_   512
#define RANK_  128
#define VOCAB_ 32000
#define TM1    47
#define NROWS  (TM1*B_)     /* 1504 */
#define NRPAD  1536
#define G4     (4*H_)       /* 4096 */
#define K0_    2560
#define KL_    2048         /* in-loop K for both gates */
#define K1_    2048
#define NBLK   256          /* persistent grid */

// ---------------- scratch (device globals) ----------------------------------
__device__ __align__(16) __nv_bfloat16 g_W0b[K0_*G4];     // reordered col'=4u+g
__device__ __align__(16) __nv_bfloat16 g_W1b[K1_*G4];     // reordered
__device__ __align__(16) __nv_bfloat16 g_Eb[VOCAB_*RANK_];
__device__ __align__(16) __nv_bfloat16 g_WoB[2048*EMB_];
__device__ __align__(16) __nv_bfloat16 g_PbT[EMB_*RANK_]; // P^T, k-major [512][128]
__device__ __align__(16) __nv_bfloat16 g_Pb[RANK_*EMB_];  // P bf16 [128][512]
__device__ __align__(16) __nv_bfloat16 g_encB[S_*B_*C_];
__device__ __align__(16) __nv_bfloat16 g_embB[NRPAD*EMB_];
__device__ __align__(16) __nv_bfloat16 g_xa[2][B_*KL_];   // ping-pong [ctx|h0]
__device__ __align__(16) __nv_bfloat16 g_xb[2][B_*K1_];   // ping-pong [h0|h1]
__device__ __align__(16) __nv_bfloat16 g_featsB[NRPAD*2048];
__device__ __align__(16) __nv_bfloat16 g_hprojB[NRPAD*EMB_];
__device__ __align__(16) __nv_bfloat16 g_tmpB[NRPAD*RANK_];
__device__ float g_embW[(size_t)NRPAD*G4];                // emb @ W0emb (reordered)
__device__ float g_part0[8][B_*G4];                       // gates0: ctx q0-3, h0 q4-7
__device__ float g_part1[8][B_*G4];                       // gates1: h0 q0-3, h1 q4-7
__device__ float g_c0[B_*H_], g_c1[B_*H_];
__device__ float g_spart[8][B_*64];                       // partial attn scores
__device__ float g_tmp[NRPAD*RANK_];
__device__ float g_sumexp[NRPAD];
__device__ float g_lbl[NROWS];

// persistent-kernel sync state
__device__ int g_bar_count = 0;
__device__ volatile int g_bar_gen = 0;

// ---------------- helpers ------------------------------------------------
__device__ __forceinline__ void ldsm_x4(uint32_t* r, const void* p) {
    uint32_t a = (uint32_t)__cvta_generic_to_shared(p);
    asm volatile("ldmatrix.sync.aligned.m8n8.x4.shared.b16 {%0,%1,%2,%3}, [%4];"
        : "=r"(r[0]), "=r"(r[1]), "=r"(r[2]), "=r"(r[3]) : "r"(a));
}
__device__ __forceinline__ void ldsm_x4_t(uint32_t* r, const void* p) {
    uint32_t a = (uint32_t)__cvta_generic_to_shared(p);
    asm volatile("ldmatrix.sync.aligned.m8n8.x4.trans.shared.b16 {%0,%1,%2,%3}, [%4];"
        : "=r"(r[0]), "=r"(r[1]), "=r"(r[2]), "=r"(r[3]) : "r"(a));
}
__device__ __forceinline__ void mma_bf16(float* d, const uint32_t* a, uint32_t b0, uint32_t b1) {
    asm volatile("mma.sync.aligned.m16n8k16.row.col.f32.bf16.bf16.f32 "
        "{%0,%1,%2,%3},{%4,%5,%6,%7},{%8,%9},{%0,%1,%2,%3};"
        : "+f"(d[0]), "+f"(d[1]), "+f"(d[2]), "+f"(d[3])
        : "r"(a[0]), "r"(a[1]), "r"(a[2]), "r"(a[3]), "r"(b0), "r"(b1));
}
__device__ __forceinline__ void cp16(void* s, const void* g) {
    uint32_t sa = (uint32_t)__cvta_generic_to_shared(s);
    asm volatile("cp.async.cg.shared.global [%0], [%1], 16;" :: "r"(sa), "l"(g));
}
__device__ __forceinline__ void cp_commit()  { asm volatile("cp.async.commit_group;"); }
__device__ __forceinline__ void cp_wait2()   { asm volatile("cp.async.wait_group 2;"); }
__device__ __forceinline__ void cp_waitall() { asm volatile("cp.async.wait_all;"); }

__device__ __forceinline__ float tanhfast(float x) {
    float r; asm("tanh.approx.f32 %0, %1;" : "=f"(r) : "f"(x)); return r;
}
__device__ __forceinline__ float sigf(float x) { return 0.5f*tanhfast(0.5f*x) + 0.5f; }

__device__ __forceinline__ float fexp(float x) {
    float y = x * 1.44269504088896341f;
    y = fminf(fmaxf(y, -120.f), 120.f);
    float n = rintf(y);
    float f = y - n;
    float p = 1.53386992e-4f;
    p = fmaf(p, f, 1.33938367e-3f);
    p = fmaf(p, f, 9.61843445e-3f);
    p = fmaf(p, f, 5.55041086e-2f);
    p = fmaf(p, f, 2.40226507e-1f);
    p = fmaf(p, f, 6.93147181e-1f);
    p = fmaf(p, f, 1.0f);
    int e = (int)n;
    return p * __int_as_float((e + 127) << 23);
}

// grid-wide flat barrier, nanosleep spin
__device__ __forceinline__ void gsync() {
    __syncthreads();
    if (threadIdx.x == 0) {
        __threadfence();
        int gen = g_bar_gen;
        if (atomicAdd(&g_bar_count, 1) == NBLK - 1) {
            g_bar_count = 0;
            __threadfence();
            g_bar_gen = gen + 1;
        } else {
            while (g_bar_gen == gen) __nanosleep(64);
        }
    }
    __syncthreads();
}

// ---------------- weight reorder (gates) + linear convert ----------------------
__global__ void reorder_w(const float* __restrict__ W0, const float* __restrict__ U0,
                          const float* __restrict__ W1, const float* __restrict__ U1) {
    int idx = blockIdx.x*256 + threadIdx.x;
    const int tot0 = K0_*1024;
    const int tot1 = K1_*1024;
    const float* src; __nv_bfloat16* d;
    int u;
    if (idx < tot0) {
        int k = idx >> 10; u = idx & 1023;
        src = (k < 1536) ? (W0 + (size_t)k*G4) : (U0 + (size_t)(k-1536)*G4);
        d = g_W0b + (size_t)k*G4 + u*4;
    } else if (idx < tot0 + tot1) {
        int j = idx - tot0;
        int k = j >> 10; u = j & 1023;
        src = (k < 1024) ? (W1 + (size_t)k*G4) : (U1 + (size_t)(k-1024)*G4);
        d = g_W1b + (size_t)k*G4 + u*4;
    } else return;
    __nv_bfloat162 p0(__float2bfloat16_rn(src[u]),        __float2bfloat16_rn(src[1024+u]));
    __nv_bfloat162 p1(__float2bfloat16_rn(src[2048+u]),   __float2bfloat16_rn(src[3072+u]));
    *(__nv_bfloat162*)(d)   = p0;
    *(__nv_bfloat162*)(d+2) = p1;
}

#define EE   (VOCAB_*RANK_)
#define WOE  (2048*EMB_)
#define ENCE (S_*B_*C_)
#define CLT  (EE + WOE + ENCE)
__global__ void convert_lin(const float* __restrict__ E, const float* __restrict__ Wo,
                            const float* __restrict__ enc) {
    long long i4 = ((long long)blockIdx.x*256 + threadIdx.x) * 4;
    if (i4 >= CLT) return;
    const float* src; __nv_bfloat16* dst;
    if (i4 < EE)            { src = E + i4;               dst = g_Eb  + i4; }
    else if (i4 < EE + WOE) { src = Wo + (i4-EE);         dst = g_WoB + (i4-EE); }
    else                    { src = enc + (i4-EE-WOE);    dst = g_encB + (i4-EE-WOE); }
    float4 v = *(const float4*)src;
    __nv_bfloat162* d2 = (__nv_bfloat162*)dst;
    d2[0] = __nv_bfloat162(__float2bfloat16_rn(v.x), __float2bfloat16_rn(v.y));
    d2[1] = __nv_bfloat162(__float2bfloat16_rn(v.z), __float2bfloat16_rn(v.w));
}

// P converts: g_PbT[k][c] = bf16(P[c][k]) ; g_Pb = bf16(P)
__global__ void pt_convert(const float* __restrict__ P) {
    int idx = blockIdx.x*256 + threadIdx.x;    // 131072
    if (idx < EMB_*RANK_) {
        int k = idx >> 7, c = idx & 127;
        g_PbT[k*RANK_ + c] = __float2bfloat16_rn(P[c*EMB_ + k]);
    } else {
        int j = idx - EMB_*RANK_;
        g_Pb[j] = __float2bfloat16_rn(P[j]);
    }
}

// ---------------- embedding via bf16 mma: 128x128 tiles ---------------------------
#define EMB_TS (128*136*2)      /* 34816 */
#define SMEM_EMB (2*EMB_TS)

__global__ void __launch_bounds__(256) embed_mma(const int* __restrict__ tok) {
    extern __shared__ __align__(16) char msm[];
    typedef __nv_bfloat16 TT[128][136];
    TT* ts = (TT*)msm;
    TT* ps = (TT*)(msm + EMB_TS);
    int tid = threadIdx.x, lane = tid & 31, w = tid >> 5;
    int cbase = blockIdx.x * 128;
    int rbase = blockIdx.y * 128;
    #pragma unroll
    for (int q = 0; q < 8; q++) {
        int c = tid + q*256;
        int row = c >> 4, kc = c & 15;
        int r = rbase + row;
        int t = r >> 5, b = r & 31;
        int token = (t < TM1) ? tok[b*T_ + t] : 0;
        cp16(&(*ts)[row][kc*8], g_Eb + (size_t)token*RANK_ + kc*8);
        cp16(&(*ps)[row][kc*8], g_Pb + (size_t)row*EMB_ + cbase + kc*8);
    }
    cp_commit();
    cp_waitall();
    __syncthreads();
    int m0 = (w & 3)*32, n0 = (w >> 2)*64;
    float acc[2][8][4] = {};
    #pragma unroll
    for (int ks = 0; ks < 8; ks++) {
        uint32_t a0[4], a1[4];
        ldsm_x4(a0, &(*ts)[m0 + (lane & 15)][ks*16 + (lane >> 4)*8]);
        ldsm_x4(a1, &(*ts)[m0 + 16 + (lane & 15)][ks*16 + (lane >> 4)*8]);
        #pragma unroll
        for (int nb = 0; nb < 4; nb++) {
            uint32_t b[4];
            ldsm_x4_t(b, &(*ps)[ks*16 + (lane & 15)][n0 + nb*16 + (lane >> 4)*8]);
            mma_bf16(acc[0][nb*2],   a0, b[0], b[1]);
            mma_bf16(acc[0][nb*2+1], a0, b[2], b[3]);
            mma_bf16(acc[1][nb*2],   a1, b[0], b[1]);
            mma_bf16(acc[1][nb*2+1], a1, b[2], b[3]);
        }
    }
    #pragma unroll
    for (int mt = 0; mt < 2; mt++)
        #pragma unroll
        for (int j = 0; j < 8; j++) {
            int col = cbase + n0 + j*8 + 2*(lane & 3);
            int r = rbase + m0 + mt*16 + (lane >> 2);
            __nv_bfloat162 o0(__float2bfloat16_rn(acc[mt][j][0]), __float2bfloat16_rn(acc[mt][j][1]));
            __nv_bfloat162 o1(__float2bfloat16_rn(acc[mt][j][2]), __float2bfloat16_rn(acc[mt][j][3]));
            *(__nv_bfloat162*)&g_embB[(size_t)r*EMB_ + col]     = o0;
            *(__nv_bfloat162*)&g_embB[(size_t)(r+8)*EMB_ + col] = o1;
        }
}

// ---------------- embW = embB @ W0b[0:512] (fp32 out), 128x128 tiles --------------
#define EMBW_XS (3*128*72*2)    /* 55296 */
#define EMBW_WS (3*64*136*2)    /* 52224 */
#define SMEM_EMBW (EMBW_XS + EMBW_WS)

__global__ void __launch_bounds__(256) embw_mma() {
    extern __shared__ __align__(16) char esm[];
    typedef __nv_bfloat16 XT[128][72];
    typedef __nv_bfloat16 WT[64][136];
    XT* xs = (XT*)esm;
    WT* ws = (WT*)(esm + EMBW_XS);
    int tid = threadIdx.x, lane = tid & 31, w = tid >> 5;
    int cbase = blockIdx.x * 128;
    int rbase = blockIdx.y * 128;
    int m0 = (w & 3) * 32, n0 = (w >> 2) * 64;
    float acc[2][8][4] = {};

    auto load_chunk = [&](int ch) {
        int st = ch % 3; int kb = ch * 64;
        #pragma unroll
        for (int q = 0; q < 4; q++) {
            int c = tid + q*256;
            int row = c >> 3, kc = c & 7;
            cp16(&xs[st][row][kc*8], g_embB + (size_t)(rbase + row)*EMB_ + kb + kc*8);
        }
        #pragma unroll
        for (int q = 0; q < 4; q++) {
            int c = tid + q*256;
            int kr = c >> 4, cc = c & 15;
            cp16(&ws[st][kr][cc*8], g_W0b + (size_t)(kb + kr)*G4 + cbase + cc*8);
        }
    };
    load_chunk(0); cp_commit();
    load_chunk(1); cp_commit();
    for (int ch = 0; ch < 8; ch++) {
        asm volatile("cp.async.wait_group 1;");
        __syncthreads();
        if (ch + 2 < 8) load_chunk(ch + 2);
        cp_commit();
        int st = ch % 3;
        #pragma unroll
        for (int ks = 0; ks < 4; ks++) {
            uint32_t a0[4], a1[4];
            ldsm_x4(a0, &xs[st][m0 + (lane & 15)][ks*16 + (lane >> 4)*8]);
            ldsm_x4(a1, &xs[st][m0 + 16 + (lane & 15)][ks*16 + (lane >> 4)*8]);
            #pragma unroll
            for (int nb = 0; nb < 4; nb++) {
                uint32_t b[4];
                ldsm_x4_t(b, &ws[st][ks*16 + (lane & 15)][n0 + nb*16 + (lane >> 4)*8]);
                mma_bf16(acc[0][nb*2],   a0, b[0], b[1]);
                mma_bf16(acc[0][nb*2+1], a0, b[2], b[3]);
                mma_bf16(acc[1][nb*2],   a1, b[0], b[1]);
                mma_bf16(acc[1][nb*2+1], a1, b[2], b[3]);
            }
        }
        __syncthreads();
    }
    #pragma unroll
    for (int mt = 0; mt < 2; mt++)
        #pragma unroll
        for (int j = 0; j < 8; j++) {
            int col = cbase + n0 + j*8 + 2*(lane & 3);
            int r = rbase + m0 + mt*16 + (lane >> 2);
            *(float2*)&g_embW[(size_t)r*G4 + col]     = make_float2(acc[mt][j][0], acc[mt][j][1]);
            *(float2*)&g_embW[(size_t)(r+8)*G4 + col] = make_float2(acc[mt][j][2], acc[mt][j][3]);
        }
}

// ---------------- init ----------------------------------------------------------
__global__ void init_kernel(const float* __restrict__ enc_state, float* out) {
    int i = blockIdx.x * blockDim.x + threadIdx.x;   // 32768
    if (i < B_*H_) {
        int b = i >> 10, j = i & 1023;
        float h0v = enc_state[i];
        float h1v = enc_state[B_*H_ + i];
        g_c0[i] = 0.f; g_c1[i] = 0.f;
        __nv_bfloat16 h0b = __float2bfloat16_rn(h0v);
        __nv_bfloat16 h1b = __float2bfloat16_rn(h1v);
        g_xb[0][b*K1_ + j]        = h0b;
        g_xb[0][b*K1_ + 1024 + j] = h1b;
        g_xa[0][b*KL_ + 1024 + j] = h0b;
        g_xa[0][b*KL_ + j]        = __float2bfloat16_rn(0.f);   // ctx = 0
    }
    {
        __nv_bfloat162 z(__float2bfloat16_rn(0.f), __float2bfloat16_rn(0.f));
        *(__nv_bfloat162*)&g_featsB[(size_t)NROWS*2048 + i*2] = z;
    }
    if (i < NRPAD) g_sumexp[i] = 0.f;
    if (i == 0) { g_bar_count = 0; g_bar_gen = 0; out[0] = 0.f; }
}

// ================= persistent step loop ==========================================
#define XS_BYTES (4*32*72*2)
#define WS_BYTES (4*64*72*2)
#define SMEM_STEP (XS_BYTES + WS_BYTES)

// quarter-split gates GEMM: K=256 (4 chunks of 64), one (ctile,split) per block
__device__ void gates_sub(char* sraw, int bid,
                          const __nv_bfloat16* __restrict__ X,
                          const __nv_bfloat16* __restrict__ W,
                          int kstart, float* __restrict__ gp) {
    constexpr int NCH = 4;
    typedef __nv_bfloat16 XsT[32][72];
    typedef __nv_bfloat16 WsT[64][72];
    XsT* xs = (XsT*)sraw;
    WsT* ws = (WsT*)(sraw + XS_BYTES);
    int tid = threadIdx.x, lane = tid & 31, w = tid >> 5;
    int cbase = (bid & 63) * 64;
    int n0 = w * 16;
    float acc[2][2][4] = {};

    auto load_chunk = [&](int ch) {
        int st = ch & 3; int kb = kstart + ch*64;
        #pragma unroll
        for (int q = 0; q < 2; q++) {
            int c = tid*2 + q;
            int row = c >> 3, kc = c & 7;
            cp16(&xs[st][row][kc*8], X + row*KL_ + kb + kc*8);
        }
        #pragma unroll
        for (int q = 0; q < 4; q++) {
            int c = tid + q*128;
            int row = c >> 3, cc = c & 7;
            cp16(&ws[st][row][cc*8], W + (size_t)(kb + row)*G4 + cbase + cc*8);
        }
    };
    load_chunk(0); cp_commit();
    load_chunk(1); cp_commit();
    load_chunk(2); cp_commit();
    for (int ch = 0; ch < NCH; ch++) {
        cp_wait2();
        __syncthreads();
        if (ch + 3 < NCH) load_chunk(ch + 3);
        cp_commit();
        int st = ch & 3;
        #pragma unroll
        for (int ks = 0; ks < 4; ks++) {
            uint32_t a0[4], a1[4], b[4];
            ldsm_x4(a0, &xs[st][(lane & 15)][ks*16 + (lane >> 4)*8]);
            ldsm_x4(a1, &xs[st][16 + (lane & 15)][ks*16 + (lane >> 4)*8]);
            ldsm_x4_t(b, &ws[st][ks*16 + (lane & 15)][n0 + (lane >> 4)*8]);
            mma_bf16(acc[0][0], a0, b[0], b[1]);
            mma_bf16(acc[0][1], a0, b[2], b[3]);
            mma_bf16(acc[1][0], a1, b[0], b[1]);
            mma_bf16(acc[1][1], a1, b[2], b[3]);
        }
    }
    cp_waitall();
    #pragma unroll
    for (int mt = 0; mt < 2; mt++)
        #pragma unroll
        for (int nt = 0; nt < 2; nt++) {
            int row = mt*16 + (lane >> 2);
            int col = cbase + n0 + nt*8 + 2*(lane & 3);
            *(float2*)&gp[(size_t)row*G4 + col]     = make_float2(acc[mt][nt][0], acc[mt][nt][1]);
            *(float2*)&gp[(size_t)(row+8)*G4 + col] = make_float2(acc[mt][nt][2], acc[mt][nt][3]);
        }
}

// cell0 tail: 256 blocks, each (b = bid&31, 128-unit slice); sums 8 partials
__device__ void cell0_tail(int bid, int t, int p, const float* __restrict__ bias) {
    int b  = bid & 31;
    int u  = (bid >> 5)*128 + threadIdx.x;
    float4 ev = *(const float4*)&g_embW[((size_t)(t*B_ + b))*G4 + 4*u];
    float gi = bias[u]        + ev.x;
    float gf = bias[1024 + u] + ev.y;
    float gg = bias[2048 + u] + ev.z;
    float go = bias[3072 + u] + ev.w;
    #pragma unroll
    for (int pt = 0; pt < 8; pt++) {
        float4 gv = __ldcg((const float4*)&g_part0[pt][(size_t)b*G4 + 4*u]);
        gi += gv.x; gf += gv.y; gg += gv.z; go += gv.w;
    }
    float c = g_c0[b*H_ + u];
    float cn = sigf(gf)*c + sigf(gi)*tanhfast(gg);
    float hn = sigf(go)*tanhfast(cn);
    g_c0[b*H_ + u] = cn;
    __nv_bfloat16 hb = __float2bfloat16_rn(hn);
    g_xb[p][b*K1_ + u] = hb;                 // gates1-h0 input this step
    g_xa[1-p][b*KL_ + 1024 + u] = hb;        // h0 next step
}

// cell1 + partial attention scores tail: (b = bid>>3, 128-unit slice), 8 partials
__device__ void cell1_tail(float* hs, int bid, int t, int p,
                           const float* __restrict__ bias,
                           const int* __restrict__ enc_lens) {
    int b     = bid >> 3;
    int slice = bid & 7;
    int tid = threadIdx.x;
    {
        int u = slice*128 + tid;
        float gi = bias[u], gf = bias[1024+u], gg = bias[2048+u], go = bias[3072+u];
        #pragma unroll
        for (int pt = 0; pt < 8; pt++) {
            float4 gv = __ldcg((const float4*)&g_part1[pt][(size_t)b*G4 + 4*u]);
            gi += gv.x; gf += gv.y; gg += gv.z; go += gv.w;
        }
        float c = g_c1[b*H_ + u];
        float cn = sigf(gf)*c + sigf(gi)*tanhfast(gg);
        float hn = sigf(go)*tanhfast(cn);
        g_c1[b*H_ + u] = cn;
        __nv_bfloat16 hb = __float2bfloat16_rn(hn);
        g_xb[1-p][b*K1_ + 1024 + u] = hb;          // h1 next step
        g_featsB[(size_t)(t*B_ + b)*2048 + u] = hb;
        hs[tid] = hn;
    }
    __syncthreads();
    int w = tid >> 5, lane = tid & 31;
    int len = enc_lens[b];
    #pragma unroll
    for (int i = 0; i < 14; i++) {
        int s = w*14 + i;
        if (s < len) {
            const __nv_bfloat16* e = g_encB + ((size_t)(s*B_ + b) << 10) + slice*128;
            uint2 v = *(const uint2*)(e + lane*4);
            const __nv_bfloat162* p2 = (const __nv_bfloat162*)&v;
            float2 f0 = __bfloat1622float2(p2[0]);
            float2 f1 = __bfloat1622float2(p2[1]);
            float a = f0.x*hs[lane*4] + f0.y*hs[lane*4+1]
                    + f1.x*hs[lane*4+2] + f1.y*hs[lane*4+3];
            #pragma unroll
            for (int o = 16; o; o >>= 1) a += __shfl_xor_sync(0xffffffffu, a, o);
            if (lane == 0) g_spart[slice][b*64 + s] = a;
        }
    }
}

// attention finish: softmax + ctx, (b = bid>>3, 128-col slice)
__device__ void attn_fin(float* sc, int bid, int t, int p,
                         const int* __restrict__ enc_lens) {
    int b  = bid >> 3;
    int c0 = (bid & 7)*128;
    int tid = threadIdx.x;
    int len = enc_lens[b];
    if (tid < 64) {
        float v = -1.0e30f;
        if (tid < len) {
            v = 0.f;
            #pragma unroll
            for (int k = 0; k < 8; k++) v += __ldcg(&g_spart[k][b*64 + tid]);
        }
        sc[tid] = v;
    }
    __syncthreads();
    if (tid < 32) {
        int lane = tid;
        float v0 = sc[lane];
        float v1 = (lane + 32 < S_) ? sc[lane + 32] : -1.0e30f;
        float m = fmaxf(v0, v1);
        #pragma unroll
        for (int o = 16; o; o >>= 1) m = fmaxf(m, __shfl_xor_sync(0xffffffffu, m, o));
        float e0 = __expf(v0 - m);
        float e1 = (lane + 32 < S_) ? __expf(v1 - m) : 0.f;
        float sum = e0 + e1;
        #pragma unroll
        for (int o = 16; o; o >>= 1) sum += __shfl_xor_sync(0xffffffffu, sum, o);
        sc[lane] = e0 / sum;
        if (lane + 32 < S_) sc[lane + 32] = e1 / sum;
    }
    __syncthreads();
    int col = c0 + tid;
    float a = 0.f;
    #pragma unroll 8
    for (int s = 0; s < S_; s++)
        a = fmaf(sc[s], __bfloat162float(g_encB[((size_t)(s*B_ + b) << 10) + col]), a);
    __nv_bfloat16 ab = __float2bfloat16_rn(a);
    g_featsB[(size_t)(t*B_ + b)*2048 + 1024 + col] = ab;
    g_xa[1-p][b*KL_ + col] = ab;              // ctx next step
}

__global__ void __launch_bounds__(128, 2) step_loop(const float* __restrict__ b0,
                                                    const float* __restrict__ b1,
                                                    const int* __restrict__ enc_lens) {
    extern __shared__ __align__(16) char sraw[];
    __shared__ float s_hs[128];
    __shared__ float s_sc[64];
    int bid = blockIdx.x;
    int split = bid >> 6;                    // 0..3
    const __nv_bfloat16* W0L = g_W0b + (size_t)512*G4;

    // prologue: gates0-h0(0) from xa[0]
    gates_sub(sraw, bid, g_xa[0], W0L, 1024 + split*256, g_part0[4 + split]);
    gsync();

    for (int t = 0; t < TM1; t++) {
        int p = t & 1;
        // P_A: gates0-ctx(t)
        gates_sub(sraw, bid, g_xa[p], W0L, split*256, g_part0[split]);
        gsync();
        // P_B: gates1-h1(t), then cell0(t)
        gates_sub(sraw, bid, g_xb[p], g_W1b, 1024 + split*256, g_part1[4 + split]);
        cell0_tail(bid, t, p, b0);
        gsync();
        // P_C: gates1-h0(t)
        gates_sub(sraw, bid, g_xb[p], g_W1b, split*256, g_part1[split]);
        gsync();
        // P_D: gates0-h0(t+1), then cell1(t)+scores
        gates_sub(sraw, bid, g_xa[1-p], W0L, 1024 + split*256, g_part0[4 + split]);
        cell1_tail(s_hs, bid, t, p, b1, enc_lens);
        gsync();
        // P_E: attn_fin(t)
        attn_fin(s_sc, bid, t, p, enc_lens);
        gsync();
    }
}

// ---------------- hproj = tanh(featsB @ WoB + bo), 128x64 tiles, bf16 out ----------
#define HP_XS (3*128*72*2)    /* 55296 */
#define HP_WS (3*64*72*2)     /* 27648 */
#define SMEM_HP (HP_XS + HP_WS)

__global__ void __launch_bounds__(256) hproj_mma(const float* __restrict__ bo) {
    extern __shared__ __align__(16) char hsm[];
    typedef __nv_bfloat16 XT[128][72];
    typedef __nv_bfloat16 WT[64][72];
    XT* xs = (XT*)hsm;
    WT* ws = (WT*)(hsm + HP_XS);
    int tid = threadIdx.x, lane = tid & 31, w = tid >> 5;
    int cbase = blockIdx.x * 64;
    int rbase = blockIdx.y * 128;
    int m0 = (w & 3) * 32, n0 = (w >> 2) * 32;
    float acc[2][4][4] = {};

    auto load_chunk = [&](int ch) {
        int st = ch % 3; int kb = ch * 64;
        #pragma unroll
        for (int q = 0; q < 4; q++) {
            int c = tid + q*256;
            int row = c >> 3, kc = c & 7;
            cp16(&xs[st][row][kc*8], g_featsB + (size_t)(rbase + row)*2048 + kb + kc*8);
        }
        #pragma unroll
        for (int q = 0; q < 2; q++) {
            int c = tid + q*256;
            int kr = c >> 3, cc = c & 7;
            cp16(&ws[st][kr][cc*8], g_WoB + (size_t)(kb + kr)*EMB_ + cbase + cc*8);
        }
    };
    load_chunk(0); cp_commit();
    load_chunk(1); cp_commit();
    for (int ch = 0; ch < 32; ch++) {
        asm volatile("cp.async.wait_group 1;");
        __syncthreads();
        if (ch + 2 < 32) load_chunk(ch + 2);
        cp_commit();
        int st = ch % 3;
        #pragma unroll
        for (int ks = 0; ks < 4; ks++) {
            uint32_t a0[4], a1[4];
            ldsm_x4(a0, &xs[st][m0 + (lane & 15)][ks*16 + (lane >> 4)*8]);
            ldsm_x4(a1, &xs[st][m0 + 16 + (lane & 15)][ks*16 + (lane >> 4)*8]);
            #pragma unroll
            for (int nb = 0; nb < 2; nb++) {
                uint32_t b[4];
                ldsm_x4_t(b, &ws[st][ks*16 + (lane & 15)][n0 + nb*16 + (lane >> 4)*8]);
                mma_bf16(acc[0][nb*2],   a0, b[0], b[1]);
                mma_bf16(acc[0][nb*2+1], a0, b[2], b[3]);
                mma_bf16(acc[1][nb*2],   a1, b[0], b[1]);
                mma_bf16(acc[1][nb*2+1], a1, b[2], b[3]);
            }
        }
        __syncthreads();
    }
    #pragma unroll
    for (int mt = 0; mt < 2; mt++)
        #pragma unroll
        for (int j = 0; j < 4; j++) {
            int col = cbase + n0 + j*8 + 2*(lane & 3);
            float b0v = bo[col], b1v = bo[col+1];
            int r = rbase + m0 + mt*16 + (lane >> 2);
            __nv_bfloat162 o0(__float2bfloat16_rn(tanhf(acc[mt][j][0] + b0v)),
                              __float2bfloat16_rn(tanhf(acc[mt][j][1] + b1v)));
            __nv_bfloat162 o1(__float2bfloat16_rn(tanhf(acc[mt][j][2] + b0v)),
                              __float2bfloat16_rn(tanhf(acc[mt][j][3] + b1v)));
            *(__nv_bfloat162*)&g_hprojB[(size_t)r*EMB_ + col]     = o0;
            *(__nv_bfloat162*)&g_hprojB[(size_t)(r+8)*EMB_ + col] = o1;
        }
}

// ---------------- tmp = hprojB @ PbT (128x128 tiles, fp32+bf16 out) ----------------
#define TP_XS (3*128*72*2)    /* 55296 */
#define TP_WS (3*64*136*2)    /* 52224 */
#define SMEM_TP (TP_XS + TP_WS)

__global__ void __launch_bounds__(256) tmp_mma() {
    extern __shared__ __align__(16) char tsm[];
    typedef __nv_bfloat16 XT[128][72];
    typedef __nv_bfloat16 WT[64][136];
    XT* xs = (XT*)tsm;
    WT* ws = (WT*)(tsm + TP_XS);
    int tid = threadIdx.x, lane = tid & 31, w = tid >> 5;
    int rbase = blockIdx.x * 128;
    int m0 = (w & 3) * 32, n0 = (w >> 2) * 64;
    float acc[2][8][4] = {};

    auto load_chunk = [&](int ch) {
        int st = ch % 3; int kb = ch * 64;
        #pragma unroll
        for (int q = 0; q < 4; q++) {
            int c = tid + q*256;
            int row = c >> 3, kc = c & 7;
            cp16(&xs[st][row][kc*8], g_hprojB + (size_t)(rbase + row)*EMB_ + kb + kc*8);
        }
        #pragma unroll
        for (int q = 0; q < 4; q++) {
            int c = tid + q*256;
            int kr = c >> 4, cc = c & 15;
            cp16(&ws[st][kr][cc*8], g_PbT + (size_t)(kb + kr)*RANK_ + cc*8);
        }
    };
    load_chunk(0); cp_commit();
    load_chunk(1); cp_commit();
    for (int ch = 0; ch < 8; ch++) {
        asm volatile("cp.async.wait_group 1;");
        __syncthreads();
        if (ch + 2 < 8) load_chunk(ch + 2);
        cp_commit();
        int st = ch % 3;
        #pragma unroll
        for (int ks = 0; ks < 4; ks++) {
            uint32_t a0[4], a1[4];
            ldsm_x4(a0, &xs[st][m0 + (lane & 15)][ks*16 + (lane >> 4)*8]);
            ldsm_x4(a1, &xs[st][m0 + 16 + (lane & 15)][ks*16 + (lane >> 4)*8]);
            #pragma unroll
            for (int nb = 0; nb < 4; nb++) {
                uint32_t b[4];
                ldsm_x4_t(b, &ws[st][ks*16 + (lane & 15)][n0 + nb*16 + (lane >> 4)*8]);
                mma_bf16(acc[0][nb*2],   a0, b[0], b[1]);
                mma_bf16(acc[0][nb*2+1], a0, b[2], b[3]);
                mma_bf16(acc[1][nb*2],   a1, b[0], b[1]);
                mma_bf16(acc[1][nb*2+1], a1, b[2], b[3]);
            }
        }
        __syncthreads();
    }
    #pragma unroll
    for (int mt = 0; mt < 2; mt++)
        #pragma unroll
        for (int j = 0; j < 8; j++) {
            int col = n0 + j*8 + 2*(lane & 3);
            int r = rbase + m0 + mt*16 + (lane >> 2);
            *(float2*)&g_tmp[(size_t)r*RANK_ + col]     = make_float2(acc[mt][j][0], acc[mt][j][1]);
            *(float2*)&g_tmp[(size_t)(r+8)*RANK_ + col] = make_float2(acc[mt][j][2], acc[mt][j][3]);
            __nv_bfloat162 t0(__float2bfloat16_rn(acc[mt][j][0]), __float2bfloat16_rn(acc[mt][j][1]));
            __nv_bfloat162 t1(__float2bfloat16_rn(acc[mt][j][2]), __float2bfloat16_rn(acc[mt][j][3]));
            *(__nv_bfloat162*)&g_tmpB[(size_t)r*RANK_ + col]     = t0;
            *(__nv_bfloat162*)&g_tmpB[(size_t)(r+8)*RANK_ + col] = t1;
        }
}

// ---------------- label logit --------------------------------------------------------
__global__ void label_kernel(const int* __restrict__ tok, const float* __restrict__ E) {
    int r = blockIdx.x*8 + (threadIdx.x >> 5);
    if (r >= NROWS) return;
    int lane = threadIdx.x & 31;
    int t = r / B_, b = r % B_;
    int lbl = tok[b*T_ + t + 1];
    float a = 0.f;
    for (int e = lane; e < RANK_; e += 32)
        a += g_tmp[(size_t)r*RANK_ + e] * E[(size_t)lbl*RANK_ + e];
    #pragma unroll
    for (int o = 16; o; o >>= 1) a += __shfl_xor_sync(0xffffffffu, a, o);
    if (lane == 0) g_lbl[r] = a;
}

// ---------------- sumexp via bf16 mma: 128 rows x 128 vocab per block ----------------
#define SE_TS (128*136*2)       /* 34816 */
#define SMEM_SE (2*SE_TS)

__global__ void __launch_bounds__(256) sumexp_mma() {
    extern __shared__ __align__(16) char ssm[];
    typedef __nv_bfloat16 TT[128][136];
    TT* ts = (TT*)ssm;
    TT* es = (TT*)(ssm + SE_TS);
    int tid = threadIdx.x, lane = tid & 31, w = tid >> 5;
    int vbase = blockIdx.x * 128, rbase = blockIdx.y * 128;
    #pragma unroll
    for (int q = 0; q < 8; q++) {
        int c = tid + q*256;
        int row = c >> 4, kc = c & 15;
        *(uint4*)&(*ts)[row][kc*8] = *(const uint4*)&g_tmpB[(size_t)(rbase + row)*RANK_ + kc*8];
        *(uint4*)&(*es)[row][kc*8] = *(const uint4*)&g_Eb[(size_t)(vbase + row)*RANK_ + kc*8];
    }
    __syncthreads();
    int m0 = (w & 3)*32, n0 = (w >> 2)*64;
    float acc[2][8][4] = {};
    #pragma unroll
    for (int ks = 0; ks < 8; ks++) {
        uint32_t a0[4], a1[4];
        ldsm_x4(a0, &(*ts)[m0 + (lane & 15)][ks*16 + (lane >> 4)*8]);
        ldsm_x4(a1, &(*ts)[m0 + 16 + (lane & 15)][ks*16 + (lane >> 4)*8]);
        #pragma unroll
        for (int nb = 0; nb < 4; nb++) {
            uint32_t b[4];
            ldsm_x4(b, &(*es)[n0 + nb*16 + (lane & 15)][ks*16 + (lane >> 4)*8]);
            mma_bf16(acc[0][nb*2],   a0, b[0], b[2]);
            mma_bf16(acc[0][nb*2+1], a0, b[1], b[3]);
            mma_bf16(acc[1][nb*2],   a1, b[0], b[2]);
            mma_bf16(acc[1][nb*2+1], a1, b[1], b[3]);
        }
    }
    #pragma unroll
    for (int mt = 0; mt < 2; mt++) {
        float sA = 0.f, sB = 0.f;
        #pragma unroll
        for (int j = 0; j < 8; j++) {
            sA += fexp(acc[mt][j][0]) + fexp(acc[mt][j][1]);
            sB += fexp(acc[mt][j][2]) + fexp(acc[mt][j][3]);
        }
        sA += __shfl_xor_sync(0xffffffffu, sA, 1);
        sA += __shfl_xor_sync(0xffffffffu, sA, 2);
        sB += __shfl_xor_sync(0xffffffffu, sB, 1);
        sB += __shfl_xor_sync(0xffffffffu, sB, 2);
        if ((lane & 3) == 0) {
            int row = rbase + m0 + mt*16 + (lane >> 2);
            atomicAdd(&g_sumexp[row], sA);
            atomicAdd(&g_sumexp[row + 8], sB);
        }
    }
}

// ---------------- final loss ---------------------------------------------------------
__global__ void loss_kernel(const int* __restrict__ tgt_lens, float* out) {
    int r = blockIdx.x*blockDim.x + threadIdx.x;
    if (r >= NROWS) return;
    int t = r / B_, b = r % B_;
    if (t < tgt_lens[b] - 1) {
        float nll = logf(g_sumexp[r]) - g_lbl[r];
        atomicAdd(out, nll);
    }
}

// ---------------- launch ----------------------------------------------------------------
extern "C" void kernel_launch(void* const* d_in, const int* in_sizes, int n_in,
                              void* d_out, int out_size) {
    const float* encoded   = (const float*)d_in[0];
    const float* enc_state = (const float*)d_in[1];
    const int*   tok       = (const int*)  d_in[2];
    const int*   enc_lens  = (const int*)  d_in[3];
    const int*   tgt_lens  = (const int*)  d_in[4];
    const float* E         = (const float*)d_in[5];
    const float* P         = (const float*)d_in[6];
    const float* W0        = (const float*)d_in[7];
    const float* U0        = (const float*)d_in[8];
    const float* b0        = (const float*)d_in[9];
    const float* W1        = (const float*)d_in[10];
    const float* U1        = (const float*)d_in[11];
    const float* b1        = (const float*)d_in[12];
    const float* Wo        = (const float*)d_in[13];
    const float* bo        = (const float*)d_in[14];
    float* out = (float*)d_out;

    static int s_attr_done = 0;
    if (!s_attr_done) {
        cudaFuncSetAttribute(step_loop,  cudaFuncAttributeMaxDynamicSharedMemorySize, SMEM_STEP);
        cudaFuncSetAttribute(embed_mma,  cudaFuncAttributeMaxDynamicSharedMemorySize, SMEM_EMB);
        cudaFuncSetAttribute(embw_mma,   cudaFuncAttributeMaxDynamicSharedMemorySize, SMEM_EMBW);
        cudaFuncSetAttribute(hproj_mma,  cudaFuncAttributeMaxDynamicSharedMemorySize, SMEM_HP);
        cudaFuncSetAttribute(tmp_mma,    cudaFuncAttributeMaxDynamicSharedMemorySize, SMEM_TP);
        cudaFuncSetAttribute(sumexp_mma, cudaFuncAttributeMaxDynamicSharedMemorySize, SMEM_SE);
        s_attr_done = 1;
    }

    reorder_w<<<(K0_*1024 + K1_*1024 + 255)/256, 256>>>(W0, U0, W1, U1);
    convert_lin<<<(CLT/4 + 255)/256, 256>>>(E, Wo, encoded);
    pt_convert<<<2*EMB_*RANK_/256, 256>>>(P);
    embed_mma<<<dim3(4, 12), 256, SMEM_EMB>>>(tok);
    embw_mma<<<dim3(32, 12), 256, SMEM_EMBW>>>();
    init_kernel<<<128, 256>>>(enc_state, out);

    step_loop<<<NBLK, 128, SMEM_STEP>>>(b0, b1, enc_lens);

    hproj_mma<<<dim3(8, 12), 256, SMEM_HP>>>(bo);
    tmp_mma<<<12, 256, SMEM_TP>>>();
    label_kernel<<<188, 256>>>(tok, E);
    sumexp_mma<<<dim3(250, 12), 256, SMEM_SE>>>();
    loss_kernel<<<6, 256>>>(tgt_lens, out);
}

// round 15
// speedup vs baseline: 1.0761x; 1.0761x over previous
#include <cuda_runtime.h>
#include <cuda_bf16.h>
#include <math.h>
#include <stdint.h>

#define S_     56
#define B_     32
#define C_     1024
#define T_     48
#define H_     1024
#define EMB_   512
#define RANK_  128
#define VOCAB_ 32000
#define TM1    47
#define NROWS  (TM1*B_)     /* 1504 */
#define NRPAD  1536
#define G4     (4*H_)       /* 4096 */
#define K0_    2560
#define KL_    2048         /* in-loop K for both gates */
#define K1_    2048
#define NBLK   256          /* persistent grid */
#define NSPLIT 4            /* k-splits */

// ---------------- scratch (device globals) ----------------------------------
__device__ __align__(16) __nv_bfloat16 g_W0b[K0_*G4];     // reordered col'=4u+g
__device__ __align__(16) __nv_bfloat16 g_W1b[K1_*G4];     // reordered
__device__ __align__(16) __nv_bfloat16 g_Eb[VOCAB_*RANK_];
__device__ __align__(16) __nv_bfloat16 g_WoB[2048*EMB_];
__device__ __align__(16) __nv_bfloat16 g_PbT[EMB_*RANK_]; // P^T, k-major [512][128]
__device__ __align__(16) __nv_bfloat16 g_Pb[RANK_*EMB_];  // P bf16 [128][512]
__device__ __align__(16) __nv_bfloat16 g_encB[S_*B_*C_];
__device__ __align__(16) __nv_bfloat16 g_embB[NRPAD*EMB_];
__device__ __align__(16) __nv_bfloat16 g_xa[2][B_*KL_];   // ping-pong [ctx|h0]
__device__ __align__(16) __nv_bfloat16 g_xb[2][B_*K1_];   // ping-pong [h0|h1]
__device__ __align__(16) __nv_bfloat16 g_featsB[NRPAD*2048];
__device__ __align__(16) __nv_bfloat16 g_hprojB[NRPAD*EMB_];
__device__ __align__(16) __nv_bfloat16 g_tmpB[NRPAD*RANK_];
__device__ float g_embW[(size_t)NRPAD*G4];                // emb @ W0emb (reordered)
__device__ float g_gates_part[NSPLIT][B_*G4];
__device__ float g_c0[B_*H_], g_c1[B_*H_];
__device__ float g_spart[8][B_*64];                       // partial attn scores
__device__ float g_tmp[NRPAD*RANK_];
__device__ float g_sumexp[NRPAD];
__device__ float g_lbl[NROWS];

// persistent-kernel sync state
__device__ int g_bar_count = 0;
__device__ volatile int g_bar_gen = 0;

// ---------------- helpers ------------------------------------------------
__device__ __forceinline__ void ldsm_x4(uint32_t* r, const void* p) {
    uint32_t a = (uint32_t)__cvta_generic_to_shared(p);
    asm volatile("ldmatrix.sync.aligned.m8n8.x4.shared.b16 {%0,%1,%2,%3}, [%4];"
        : "=r"(r[0]), "=r"(r[1]), "=r"(r[2]), "=r"(r[3]) : "r"(a));
}
__device__ __forceinline__ void ldsm_x4_t(uint32_t* r, const void* p) {
    uint32_t a = (uint32_t)__cvta_generic_to_shared(p);
    asm volatile("ldmatrix.sync.aligned.m8n8.x4.trans.shared.b16 {%0,%1,%2,%3}, [%4];"
        : "=r"(r[0]), "=r"(r[1]), "=r"(r[2]), "=r"(r[3]) : "r"(a));
}
__device__ __forceinline__ void mma_bf16(float* d, const uint32_t* a, uint32_t b0, uint32_t b1) {
    asm volatile("mma.sync.aligned.m16n8k16.row.col.f32.bf16.bf16.f32 "
        "{%0,%1,%2,%3},{%4,%5,%6,%7},{%8,%9},{%0,%1,%2,%3};"
        : "+f"(d[0]), "+f"(d[1]), "+f"(d[2]), "+f"(d[3])
        : "r"(a[0]), "r"(a[1]), "r"(a[2]), "r"(a[3]), "r"(b0), "r"(b1));
}
__device__ __forceinline__ void cp16(void* s, const void* g) {
    uint32_t sa = (uint32_t)__cvta_generic_to_shared(s);
    asm volatile("cp.async.cg.shared.global [%0], [%1], 16;" :: "r"(sa), "l"(g));
}
__device__ __forceinline__ void cp_commit()  { asm volatile("cp.async.commit_group;"); }
__device__ __forceinline__ void cp_wait2()   { asm volatile("cp.async.wait_group 2;"); }
__device__ __forceinline__ void cp_waitall() { asm volatile("cp.async.wait_all;"); }

__device__ __forceinline__ float tanhfast(float x) {
    float r; asm("tanh.approx.f32 %0, %1;" : "=f"(r) : "f"(x)); return r;
}
__device__ __forceinline__ float sigf(float x) { return 0.5f*tanhfast(0.5f*x) + 0.5f; }

__device__ __forceinline__ float fexp(float x) {
    float y = x * 1.44269504088896341f;
    y = fminf(fmaxf(y, -120.f), 120.f);
    float n = rintf(y);
    float f = y - n;
    float p = 1.53386992e-4f;
    p = fmaf(p, f, 1.33938367e-3f);
    p = fmaf(p, f, 9.61843445e-3f);
    p = fmaf(p, f, 5.55041086e-2f);
    p = fmaf(p, f, 2.40226507e-1f);
    p = fmaf(p, f, 6.93147181e-1f);
    p = fmaf(p, f, 1.0f);
    int e = (int)n;
    return p * __int_as_float((e + 127) << 23);
}

// grid-wide flat barrier, nanosleep spin
__device__ __forceinline__ void gsync() {
    __syncthreads();
    if (threadIdx.x == 0) {
        __threadfence();
        int gen = g_bar_gen;
        if (atomicAdd(&g_bar_count, 1) == NBLK - 1) {
            g_bar_count = 0;
            __threadfence();
            g_bar_gen = gen + 1;
        } else {
            while (g_bar_gen == gen) __nanosleep(64);
        }
    }
    __syncthreads();
}

// ---------------- weight reorder (gates) + linear convert ----------------------
__global__ void reorder_w(const float* __restrict__ W0, const float* __restrict__ U0,
                          const float* __restrict__ W1, const float* __restrict__ U1) {
    int idx = blockIdx.x*256 + threadIdx.x;
    const int tot0 = K0_*1024;
    const int tot1 = K1_*1024;
    const float* src; __nv_bfloat16* d;
    int u;
    if (idx < tot0) {
        int k = idx >> 10; u = idx & 1023;
        src = (k < 1536) ? (W0 + (size_t)k*G4) : (U0 + (size_t)(k-1536)*G4);
        d = g_W0b + (size_t)k*G4 + u*4;
    } else if (idx < tot0 + tot1) {
        int j = idx - tot0;
        int k = j >> 10; u = j & 1023;
        src = (k < 1024) ? (W1 + (size_t)k*G4) : (U1 + (size_t)(k-1024)*G4);
        d = g_W1b + (size_t)k*G4 + u*4;
    } else return;
    __nv_bfloat162 p0(__float2bfloat16_rn(src[u]),        __float2bfloat16_rn(src[1024+u]));
    __nv_bfloat162 p1(__float2bfloat16_rn(src[2048+u]),   __float2bfloat16_rn(src[3072+u]));
    *(__nv_bfloat162*)(d)   = p0;
    *(__nv_bfloat162*)(d+2) = p1;
}

#define EE   (VOCAB_*RANK_)
#define WOE  (2048*EMB_)
#define ENCE (S_*B_*C_)
#define CLT  (EE + WOE + ENCE)
__global__ void convert_lin(const float* __restrict__ E, const float* __restrict__ Wo,
                            const float* __restrict__ enc) {
    long long i4 = ((long long)blockIdx.x*256 + threadIdx.x) * 4;
    if (i4 >= CLT) return;
    const float* src; __nv_bfloat16* dst;
    if (i4 < EE)            { src = E + i4;               dst = g_Eb  + i4; }
    else if (i4 < EE + WOE) { src = Wo + (i4-EE);         dst = g_WoB + (i4-EE); }
    else                    { src = enc + (i4-EE-WOE);    dst = g_encB + (i4-EE-WOE); }
    float4 v = *(const float4*)src;
    __nv_bfloat162* d2 = (__nv_bfloat162*)dst;
    d2[0] = __nv_bfloat162(__float2bfloat16_rn(v.x), __float2bfloat16_rn(v.y));
    d2[1] = __nv_bfloat162(__float2bfloat16_rn(v.z), __float2bfloat16_rn(v.w));
}

// P converts: g_PbT[k][c] = bf16(P[c][k]) ; g_Pb = bf16(P)
__global__ void pt_convert(const float* __restrict__ P) {
    int idx = blockIdx.x*256 + threadIdx.x;    // 131072
    if (idx < EMB_*RANK_) {
        int k = idx >> 7, c = idx & 127;
        g_PbT[k*RANK_ + c] = __float2bfloat16_rn(P[c*EMB_ + k]);
    } else {
        int j = idx - EMB_*RANK_;
        g_Pb[j] = __float2bfloat16_rn(P[j]);
    }
}

// ---------------- embedding via bf16 mma: 128x128 tiles ---------------------------
#define EMB_TS (128*136*2)      /* 34816 */
#define SMEM_EMB (2*EMB_TS)

__global__ void __launch_bounds__(256) embed_mma(const int* __restrict__ tok) {
    extern __shared__ __align__(16) char msm[];
    typedef __nv_bfloat16 TT[128][136];
    TT* ts = (TT*)msm;
    TT* ps = (TT*)(msm + EMB_TS);
    int tid = threadIdx.x, lane = tid & 31, w = tid >> 5;
    int cbase = blockIdx.x * 128;
    int rbase = blockIdx.y * 128;
    #pragma unroll
    for (int q = 0; q < 8; q++) {
        int c = tid + q*256;
        int row = c >> 4, kc = c & 15;
        int r = rbase + row;
        int t = r >> 5, b = r & 31;
        int token = (t < TM1) ? tok[b*T_ + t] : 0;
        cp16(&(*ts)[row][kc*8], g_Eb + (size_t)token*RANK_ + kc*8);
        cp16(&(*ps)[row][kc*8], g_Pb + (size_t)row*EMB_ + cbase + kc*8);
    }
    cp_commit();
    cp_waitall();
    __syncthreads();
    int m0 = (w & 3)*32, n0 = (w >> 2)*64;
    float acc[2][8][4] = {};
    #pragma unroll
    for (int ks = 0; ks < 8; ks++) {
        uint32_t a0[4], a1[4];
        ldsm_x4(a0, &(*ts)[m0 + (lane & 15)][ks*16 + (lane >> 4)*8]);
        ldsm_x4(a1, &(*ts)[m0 + 16 + (lane & 15)][ks*16 + (lane >> 4)*8]);
        #pragma unroll
        for (int nb = 0; nb < 4; nb++) {
            uint32_t b[4];
            ldsm_x4_t(b, &(*ps)[ks*16 + (lane & 15)][n0 + nb*16 + (lane >> 4)*8]);
            mma_bf16(acc[0][nb*2],   a0, b[0], b[1]);
            mma_bf16(acc[0][nb*2+1], a0, b[2], b[3]);
            mma_bf16(acc[1][nb*2],   a1, b[0], b[1]);
            mma_bf16(acc[1][nb*2+1], a1, b[2], b[3]);
        }
    }
    #pragma unroll
    for (int mt = 0; mt < 2; mt++)
        #pragma unroll
        for (int j = 0; j < 8; j++) {
            int col = cbase + n0 + j*8 + 2*(lane & 3);
            int r = rbase + m0 + mt*16 + (lane >> 2);
            __nv_bfloat162 o0(__float2bfloat16_rn(acc[mt][j][0]), __float2bfloat16_rn(acc[mt][j][1]));
            __nv_bfloat162 o1(__float2bfloat16_rn(acc[mt][j][2]), __float2bfloat16_rn(acc[mt][j][3]));
            *(__nv_bfloat162*)&g_embB[(size_t)r*EMB_ + col]     = o0;
            *(__nv_bfloat162*)&g_embB[(size_t)(r+8)*EMB_ + col] = o1;
        }
}

// ---------------- embW = embB @ W0b[0:512] (fp32 out), 128x128 tiles, 2-stage ------
#define EMBW_XS (2*128*72*2)    /* 36864 */
#define EMBW_WS (2*64*136*2)    /* 34816 */
#define SMEM_EMBW (EMBW_XS + EMBW_WS)

__global__ void __launch_bounds__(256) embw_mma() {
    extern __shared__ __align__(16) char esm[];
    typedef __nv_bfloat16 XT[128][72];
    typedef __nv_bfloat16 WT[64][136];
    XT* xs = (XT*)esm;
    WT* ws = (WT*)(esm + EMBW_XS);
    int tid = threadIdx.x, lane = tid & 31, w = tid >> 5;
    int cbase = blockIdx.x * 128;
    int rbase = blockIdx.y * 128;
    int m0 = (w & 3) * 32, n0 = (w >> 2) * 64;
    float acc[2][8][4] = {};

    auto load_chunk = [&](int ch) {
        int st = ch & 1; int kb = ch * 64;
        #pragma unroll
        for (int q = 0; q < 4; q++) {
            int c = tid + q*256;
            int row = c >> 3, kc = c & 7;
            cp16(&xs[st][row][kc*8], g_embB + (size_t)(rbase + row)*EMB_ + kb + kc*8);
        }
        #pragma unroll
        for (int q = 0; q < 4; q++) {
            int c = tid + q*256;
            int kr = c >> 4, cc = c & 15;
            cp16(&ws[st][kr][cc*8], g_W0b + (size_t)(kb + kr)*G4 + cbase + cc*8);
        }
    };
    load_chunk(0); cp_commit();
    for (int ch = 0; ch < 8; ch++) {
        if (ch + 1 < 8) { load_chunk(ch + 1); cp_commit(); }
        if (ch + 1 < 8) asm volatile("cp.async.wait_group 1;");
        else            asm volatile("cp.async.wait_group 0;");
        __syncthreads();
        int st = ch & 1;
        #pragma unroll
        for (int ks = 0; ks < 4; ks++) {
            uint32_t a0[4], a1[4];
            ldsm_x4(a0, &xs[st][m0 + (lane & 15)][ks*16 + (lane >> 4)*8]);
            ldsm_x4(a1, &xs[st][m0 + 16 + (lane & 15)][ks*16 + (lane >> 4)*8]);
            #pragma unroll
            for (int nb = 0; nb < 4; nb++) {
                uint32_t b[4];
                ldsm_x4_t(b, &ws[st][ks*16 + (lane & 15)][n0 + nb*16 + (lane >> 4)*8]);
                mma_bf16(acc[0][nb*2],   a0, b[0], b[1]);
                mma_bf16(acc[0][nb*2+1], a0, b[2], b[3]);
                mma_bf16(acc[1][nb*2],   a1, b[0], b[1]);
                mma_bf16(acc[1][nb*2+1], a1, b[2], b[3]);
            }
        }
        __syncthreads();
    }
    #pragma unroll
    for (int mt = 0; mt < 2; mt++)
        #pragma unroll
        for (int j = 0; j < 8; j++) {
            int col = cbase + n0 + j*8 + 2*(lane & 3);
            int r = rbase + m0 + mt*16 + (lane >> 2);
            *(float2*)&g_embW[(size_t)r*G4 + col]     = make_float2(acc[mt][j][0], acc[mt][j][1]);
            *(float2*)&g_embW[(size_t)(r+8)*G4 + col] = make_float2(acc[mt][j][2], acc[mt][j][3]);
        }
}

// ---------------- init ----------------------------------------------------------
__global__ void init_kernel(const float* __restrict__ enc_state, float* out) {
    int i = blockIdx.x * blockDim.x + threadIdx.x;   // 32768
    if (i < B_*H_) {
        int b = i >> 10, j = i & 1023;
        float h0v = enc_state[i];
        float h1v = enc_state[B_*H_ + i];
        g_c0[i] = 0.f; g_c1[i] = 0.f;
        __nv_bfloat16 h0b = __float2bfloat16_rn(h0v);
        __nv_bfloat16 h1b = __float2bfloat16_rn(h1v);
        g_xb[0][b*K1_ + j]        = h0b;
        g_xb[0][b*K1_ + 1024 + j] = h1b;
        g_xa[0][b*KL_ + 1024 + j] = h0b;
        g_xa[0][b*KL_ + j]        = __float2bfloat16_rn(0.f);   // ctx = 0
    }
    {
        __nv_bfloat162 z(__float2bfloat16_rn(0.f), __float2bfloat16_rn(0.f));
        *(__nv_bfloat162*)&g_featsB[(size_t)NROWS*2048 + i*2] = z;
    }
    if (i < NRPAD) g_sumexp[i] = 0.f;
    if (i == 0) { g_bar_count = 0; g_bar_gen = 0; out[0] = 0.f; }
}

// ================= persistent step loop (R8/R13 structure — best) ==================
#define XS_BYTES (4*32*72*2)
#define WS_BYTES (4*64*72*2)
#define SMEM_STEP (XS_BYTES + WS_BYTES)

// gates GEMM (K=2048, k-split 4, chunks of 64, depth-3 pipeline)
template<int WHICH>
__device__ void gates_phase(char* sraw, int bid, int p) {
    constexpr int NCH = 8;
    typedef __nv_bfloat16 XsT[32][72];
    typedef __nv_bfloat16 WsT[64][72];
    XsT* xs = (XsT*)sraw;
    WsT* ws = (WsT*)(sraw + XS_BYTES);
    const __nv_bfloat16* __restrict__ X = WHICH ? g_xb[p] : g_xa[p];
    const __nv_bfloat16* __restrict__ W = WHICH ? g_W1b : (g_W0b + (size_t)512*G4);
    int tid = threadIdx.x, lane = tid & 31, w = tid >> 5;
    int ctile  = bid & 63;
    int ksplit = bid >> 6;
    int cbase  = ctile * 64;
    int kstart = ksplit * 512;
    int n0 = w * 16;
    float acc[2][2][4] = {};

    auto load_chunk = [&](int ch) {
        int st = ch & 3; int kb = kstart + ch*64;
        #pragma unroll
        for (int q = 0; q < 2; q++) {
            int c = tid*2 + q;
            int row = c >> 3, kc = c & 7;
            cp16(&xs[st][row][kc*8], X + row*KL_ + kb + kc*8);
        }
        #pragma unroll
        for (int q = 0; q < 4; q++) {
            int c = tid + q*128;
            int row = c >> 3, cc = c & 7;
            cp16(&ws[st][row][cc*8], W + (size_t)(kb + row)*G4 + cbase + cc*8);
        }
    };
    load_chunk(0); cp_commit();
    load_chunk(1); cp_commit();
    load_chunk(2); cp_commit();
    for (int ch = 0; ch < NCH; ch++) {
        cp_wait2();
        __syncthreads();
        if (ch + 3 < NCH) load_chunk(ch + 3);
        cp_commit();
        int st = ch & 3;
        #pragma unroll
        for (int ks = 0; ks < 4; ks++) {
            uint32_t a0[4], a1[4], b[4];
            ldsm_x4(a0, &xs[st][(lane & 15)][ks*16 + (lane >> 4)*8]);
            ldsm_x4(a1, &xs[st][16 + (lane & 15)][ks*16 + (lane >> 4)*8]);
            ldsm_x4_t(b, &ws[st][ks*16 + (lane & 15)][n0 + (lane >> 4)*8]);
            mma_bf16(acc[0][0], a0, b[0], b[1]);
            mma_bf16(acc[0][1], a0, b[2], b[3]);
            mma_bf16(acc[1][0], a1, b[0], b[1]);
            mma_bf16(acc[1][1], a1, b[2], b[3]);
        }
    }
    cp_waitall();
    float* gp = g_gates_part[ksplit];
    #pragma unroll
    for (int mt = 0; mt < 2; mt++)
        #pragma unroll
        for (int nt = 0; nt < 2; nt++) {
            int row = mt*16 + (lane >> 2);
            int col = cbase + n0 + nt*8 + 2*(lane & 3);
            *(float2*)&gp[(size_t)row*G4 + col]     = make_float2(acc[mt][nt][0], acc[mt][nt][1]);
            *(float2*)&gp[(size_t)(row+8)*G4 + col] = make_float2(acc[mt][nt][2], acc[mt][nt][3]);
        }
}

// cell0: 256 blocks, each (b = bid&31, 128-unit slice)
__device__ void cell0_phase(int bid, int t, int p, const float* __restrict__ bias) {
    int b  = bid & 31;
    int u  = (bid >> 5)*128 + threadIdx.x;
    float4 ev = *(const float4*)&g_embW[((size_t)(t*B_ + b))*G4 + 4*u];
    float gi = bias[u]        + ev.x;
    float gf = bias[1024 + u] + ev.y;
    float gg = bias[2048 + u] + ev.z;
    float go = bias[3072 + u] + ev.w;
    #pragma unroll
    for (int pt = 0; pt < NSPLIT; pt++) {
        float4 gv = __ldcg((const float4*)&g_gates_part[pt][(size_t)b*G4 + 4*u]);
        gi += gv.x; gf += gv.y; gg += gv.z; go += gv.w;
    }
    float c = g_c0[b*H_ + u];
    float cn = sigf(gf)*c + sigf(gi)*tanhfast(gg);
    float hn = sigf(go)*tanhfast(cn);
    g_c0[b*H_ + u] = cn;
    __nv_bfloat16 hb = __float2bfloat16_rn(hn);
    g_xb[p][b*K1_ + u] = hb;                 // gates1 input this step
    g_xa[1-p][b*KL_ + 1024 + u] = hb;        // h0 next step
}

// cell1 + partial attention scores: 256 blocks, (b = bid>>3, 128-unit slice)
__device__ void cell1_phase(float* hs, int bid, int t, int p,
                            const float* __restrict__ bias,
                            const int* __restrict__ enc_lens) {
    int b     = bid >> 3;
    int slice = bid & 7;
    int tid = threadIdx.x;
    {
        int u = slice*128 + tid;
        float gi = bias[u], gf = bias[1024+u], gg = bias[2048+u], go = bias[3072+u];
        #pragma unroll
        for (int pt = 0; pt < NSPLIT; pt++) {
            float4 gv = __ldcg((const float4*)&g_gates_part[pt][(size_t)b*G4 + 4*u]);
            gi += gv.x; gf += gv.y; gg += gv.z; go += gv.w;
        }
        float c = g_c1[b*H_ + u];
        float cn = sigf(gf)*c + sigf(gi)*tanhfast(gg);
        float hn = sigf(go)*tanhfast(cn);
        g_c1[b*H_ + u] = cn;
        __nv_bfloat16 hb = __float2bfloat16_rn(hn);
        g_xb[1-p][b*K1_ + 1024 + u] = hb;          // h1 next step
        g_featsB[(size_t)(t*B_ + b)*2048 + u] = hb;
        hs[tid] = hn;
    }
    __syncthreads();
    int w = tid >> 5, lane = tid & 31;
    int len = enc_lens[b];
    #pragma unroll
    for (int i = 0; i < 14; i++) {
        int s = w*14 + i;
        if (s < len) {
            const __nv_bfloat16* e = g_encB + ((size_t)(s*B_ + b) << 10) + slice*128;
            uint2 v = *(const uint2*)(e + lane*4);
            const __nv_bfloat162* p2 = (const __nv_bfloat162*)&v;
            float2 f0 = __bfloat1622float2(p2[0]);
            float2 f1 = __bfloat1622float2(p2[1]);
            float a = f0.x*hs[lane*4] + f0.y*hs[lane*4+1]
                    + f1.x*hs[lane*4+2] + f1.y*hs[lane*4+3];
            #pragma unroll
            for (int o = 16; o; o >>= 1) a += __shfl_xor_sync(0xffffffffu, a, o);
            if (lane == 0) g_spart[slice][b*64 + s] = a;
        }
    }
}

// attention finish: softmax + ctx, 256 blocks, (b = bid>>3, 128-col slice)
__device__ void attn_fin(float* sc, int bid, int t, int p,
                         const int* __restrict__ enc_lens) {
    int b  = bid >> 3;
    int c0 = (bid & 7)*128;
    int tid = threadIdx.x;
    int len = enc_lens[b];
    if (tid < 64) {
        float v = -1.0e30f;
        if (tid < len) {
            v = 0.f;
            #pragma unroll
            for (int k = 0; k < 8; k++) v += __ldcg(&g_spart[k][b*64 + tid]);
        }
        sc[tid] = v;
    }
    __syncthreads();
    if (tid < 32) {
        int lane = tid;
        float v0 = sc[lane];
        float v1 = (lane + 32 < S_) ? sc[lane + 32] : -1.0e30f;
        float m = fmaxf(v0, v1);
        #pragma unroll
        for (int o = 16; o; o >>= 1) m = fmaxf(m, __shfl_xor_sync(0xffffffffu, m, o));
        float e0 = __expf(v0 - m);
        float e1 = (lane + 32 < S_) ? __expf(v1 - m) : 0.f;
        float sum = e0 + e1;
        #pragma unroll
        for (int o = 16; o; o >>= 1) sum += __shfl_xor_sync(0xffffffffu, sum, o);
        sc[lane] = e0 / sum;
        if (lane + 32 < S_) sc[lane + 32] = e1 / sum;
    }
    __syncthreads();
    int col = c0 + tid;
    float a = 0.f;
    #pragma unroll 8
    for (int s = 0; s < S_; s++)
        a = fmaf(sc[s], __bfloat162float(g_encB[((size_t)(s*B_ + b) << 10) + col]), a);
    __nv_bfloat16 ab = __float2bfloat16_rn(a);
    g_featsB[(size_t)(t*B_ + b)*2048 + 1024 + col] = ab;
    g_xa[1-p][b*KL_ + col] = ab;              // ctx next step
}

__global__ void __launch_bounds__(128, 2) step_loop(const float* __restrict__ b0,
                                                    const float* __restrict__ b1,
                                                    const int* __restrict__ enc_lens) {
    extern __shared__ __align__(16) char sraw[];
    __shared__ float s_hs[128];
    __shared__ float s_sc[64];
    int bid = blockIdx.x;
    for (int t = 0; t < TM1; t++) {
        int p = t & 1;
        gates_phase<0>(sraw, bid, p);
        gsync();
        cell0_phase(bid, t, p, b0);
        gsync();
        gates_phase<1>(sraw, bid, p);
        gsync();
        cell1_phase(s_hs, bid, t, p, b1, enc_lens);
        gsync();
        attn_fin(s_sc, bid, t, p, enc_lens);
        gsync();
    }
}

// ---------------- hproj = tanh(featsB @ WoB + bo), 128x64 tiles, bf16 out ----------
#define HP_XS (3*128*72*2)    /* 55296 */
#define HP_WS (3*64*72*2)     /* 27648 */
#define SMEM_HP (HP_XS + HP_WS)

__global__ void __launch_bounds__(256) hproj_mma(const float* __restrict__ bo) {
    extern __shared__ __align__(16) char hsm[];
    typedef __nv_bfloat16 XT[128][72];
    typedef __nv_bfloat16 WT[64][72];
    XT* xs = (XT*)hsm;
    WT* ws = (WT*)(hsm + HP_XS);
    int tid = threadIdx.x, lane = tid & 31, w = tid >> 5;
    int cbase = blockIdx.x * 64;
    int rbase = blockIdx.y * 128;
    int m0 = (w & 3) * 32, n0 = (w >> 2) * 32;
    float acc[2][4][4] = {};

    auto load_chunk = [&](int ch) {
        int st = ch % 3; int kb = ch * 64;
        #pragma unroll
        for (int q = 0; q < 4; q++) {
            int c = tid + q*256;
            int row = c >> 3, kc = c & 7;
            cp16(&xs[st][row][kc*8], g_featsB + (size_t)(rbase + row)*2048 + kb + kc*8);
        }
        #pragma unroll
        for (int q = 0; q < 2; q++) {
            int c = tid + q*256;
            int kr = c >> 3, cc = c & 7;
            cp16(&ws[st][kr][cc*8], g_WoB + (size_t)(kb + kr)*EMB_ + cbase + cc*8);
        }
    };
    load_chunk(0); cp_commit();
    load_chunk(1); cp_commit();
    for (int ch = 0; ch < 32; ch++) {
        asm volatile("cp.async.wait_group 1;");
        __syncthreads();
        if (ch + 2 < 32) load_chunk(ch + 2);
        cp_commit();
        int st = ch % 3;
        #pragma unroll
        for (int ks = 0; ks < 4; ks++) {
            uint32_t a0[4], a1[4];
            ldsm_x4(a0, &xs[st][m0 + (lane & 15)][ks*16 + (lane >> 4)*8]);
            ldsm_x4(a1, &xs[st][m0 + 16 + (lane & 15)][ks*16 + (lane >> 4)*8]);
            #pragma unroll
            for (int nb = 0; nb < 2; nb++) {
                uint32_t b[4];
                ldsm_x4_t(b, &ws[st][ks*16 + (lane & 15)][n0 + nb*16 + (lane >> 4)*8]);
                mma_bf16(acc[0][nb*2],   a0, b[0], b[1]);
                mma_bf16(acc[0][nb*2+1], a0, b[2], b[3]);
                mma_bf16(acc[1][nb*2],   a1, b[0], b[1]);
                mma_bf16(acc[1][nb*2+1], a1, b[2], b[3]);
            }
        }
        __syncthreads();
    }
    #pragma unroll
    for (int mt = 0; mt < 2; mt++)
        #pragma unroll
        for (int j = 0; j < 4; j++) {
            int col = cbase + n0 + j*8 + 2*(lane & 3);
            float b0v = bo[col], b1v = bo[col+1];
            int r = rbase + m0 + mt*16 + (lane >> 2);
            __nv_bfloat162 o0(__float2bfloat16_rn(tanhf(acc[mt][j][0] + b0v)),
                              __float2bfloat16_rn(tanhf(acc[mt][j][1] + b1v)));
            __nv_bfloat162 o1(__float2bfloat16_rn(tanhf(acc[mt][j][2] + b0v)),
                              __float2bfloat16_rn(tanhf(acc[mt][j][3] + b1v)));
            *(__nv_bfloat162*)&g_hprojB[(size_t)r*EMB_ + col]     = o0;
            *(__nv_bfloat162*)&g_hprojB[(size_t)(r+8)*EMB_ + col] = o1;
        }
}

// ---------------- tmp = hprojB @ PbT (128x128 tiles, fp32+bf16 out) ----------------
#define TP_XS (3*128*72*2)    /* 55296 */
#define TP_WS (3*64*136*2)    /* 52224 */
#define SMEM_TP (TP_XS + TP_WS)

__global__ void __launch_bounds__(256) tmp_mma() {
    extern __shared__ __align__(16) char tsm[];
    typedef __nv_bfloat16 XT[128][72];
    typedef __nv_bfloat16 WT[64][136];
    XT* xs = (XT*)tsm;
    WT* ws = (WT*)(tsm + TP_XS);
    int tid = threadIdx.x, lane = tid & 31, w = tid >> 5;
    int rbase = blockIdx.x * 128;
    int m0 = (w & 3) * 32, n0 = (w >> 2) * 64;
    float acc[2][8][4] = {};

    auto load_chunk = [&](int ch) {
        int st = ch % 3; int kb = ch * 64;
        #pragma unroll
        for (int q = 0; q < 4; q++) {
            int c = tid + q*256;
            int row = c >> 3, kc = c & 7;
            cp16(&xs[st][row][kc*8], g_hprojB + (size_t)(rbase + row)*EMB_ + kb + kc*8);
        }
        #pragma unroll
        for (int q = 0; q < 4; q++) {
            int c = tid + q*256;
            int kr = c >> 4, cc = c & 15;
            cp16(&ws[st][kr][cc*8], g_PbT + (size_t)(kb + kr)*RANK_ + cc*8);
        }
    };
    load_chunk(0); cp_commit();
    load_chunk(1); cp_commit();
    for (int ch = 0; ch < 8; ch++) {
        asm volatile("cp.async.wait_group 1;");
        __syncthreads();
        if (ch + 2 < 8) load_chunk(ch + 2);
        cp_commit();
        int st = ch % 3;
        #pragma unroll
        for (int ks = 0; ks < 4; ks++) {
            uint32_t a0[4], a1[4];
            ldsm_x4(a0, &xs[st][m0 + (lane & 15)][ks*16 + (lane >> 4)*8]);
            ldsm_x4(a1, &xs[st][m0 + 16 + (lane & 15)][ks*16 + (lane >> 4)*8]);
            #pragma unroll
            for (int nb = 0; nb < 4; nb++) {
                uint32_t b[4];
                ldsm_x4_t(b, &ws[st][ks*16 + (lane & 15)][n0 + nb*16 + (lane >> 4)*8]);
                mma_bf16(acc[0][nb*2],   a0, b[0], b[1]);
                mma_bf16(acc[0][nb*2+1], a0, b[2], b[3]);
                mma_bf16(acc[1][nb*2],   a1, b[0], b[1]);
                mma_bf16(acc[1][nb*2+1], a1, b[2], b[3]);
            }
        }
        __syncthreads();
    }
    #pragma unroll
    for (int mt = 0; mt < 2; mt++)
        #pragma unroll
        for (int j = 0; j < 8; j++) {
            int col = n0 + j*8 + 2*(lane & 3);
            int r = rbase + m0 + mt*16 + (lane >> 2);
            *(float2*)&g_tmp[(size_t)r*RANK_ + col]     = make_float2(acc[mt][j][0], acc[mt][j][1]);
            *(float2*)&g_tmp[(size_t)(r+8)*RANK_ + col] = make_float2(acc[mt][j][2], acc[mt][j][3]);
            __nv_bfloat162 t0(__float2bfloat16_rn(acc[mt][j][0]), __float2bfloat16_rn(acc[mt][j][1]));
            __nv_bfloat162 t1(__float2bfloat16_rn(acc[mt][j][2]), __float2bfloat16_rn(acc[mt][j][3]));
            *(__nv_bfloat162*)&g_tmpB[(size_t)r*RANK_ + col]     = t0;
            *(__nv_bfloat162*)&g_tmpB[(size_t)(r+8)*RANK_ + col] = t1;
        }
}

// ---------------- label logit --------------------------------------------------------
__global__ void label_kernel(const int* __restrict__ tok, const float* __restrict__ E) {
    int r = blockIdx.x*8 + (threadIdx.x >> 5);
    if (r >= NROWS) return;
    int lane = threadIdx.x & 31;
    int t = r / B_, b = r % B_;
    int lbl = tok[b*T_ + t + 1];
    float a = 0.f;
    for (int e = lane; e < RANK_; e += 32)
        a += g_tmp[(size_t)r*RANK_ + e] * E[(size_t)lbl*RANK_ + e];
    #pragma unroll
    for (int o = 16; o; o >>= 1) a += __shfl_xor_sync(0xffffffffu, a, o);
    if (lane == 0) g_lbl[r] = a;
}

// ---------------- sumexp via bf16 mma: 128 rows x 128 vocab per block ----------------
#define SE_TS (128*136*2)       /* 34816 */
#define SMEM_SE (2*SE_TS)

__global__ void __launch_bounds__(256) sumexp_mma() {
    extern __shared__ __align__(16) char ssm[];
    typedef __nv_bfloat16 TT[128][136];
    TT* ts = (TT*)ssm;
    TT* es = (TT*)(ssm + SE_TS);
    int tid = threadIdx.x, lane = tid & 31, w = tid >> 5;
    int vbase = blockIdx.x * 128, rbase = blockIdx.y * 128;
    #pragma unroll
    for (int q = 0; q < 8; q++) {
        int c = tid + q*256;
        int row = c >> 4, kc = c & 15;
        *(uint4*)&(*ts)[row][kc*8] = *(const uint4*)&g_tmpB[(size_t)(rbase + row)*RANK_ + kc*8];
        *(uint4*)&(*es)[row][kc*8] = *(const uint4*)&g_Eb[(size_t)(vbase + row)*RANK_ + kc*8];
    }
    __syncthreads();
    int m0 = (w & 3)*32, n0 = (w >> 2)*64;
    float acc[2][8][4] = {};
    #pragma unroll
    for (int ks = 0; ks < 8; ks++) {
        uint32_t a0[4], a1[4];
        ldsm_x4(a0, &(*ts)[m0 + (lane & 15)][ks*16 + (lane >> 4)*8]);
        ldsm_x4(a1, &(*ts)[m0 + 16 + (lane & 15)][ks*16 + (lane >> 4)*8]);
        #pragma unroll
        for (int nb = 0; nb < 4; nb++) {
            uint32_t b[4];
            ldsm_x4(b, &(*es)[n0 + nb*16 + (lane & 15)][ks*16 + (lane >> 4)*8]);
            mma_bf16(acc[0][nb*2],   a0, b[0], b[2]);
            mma_bf16(acc[0][nb*2+1], a0, b[1], b[3]);
            mma_bf16(acc[1][nb*2],   a1, b[0], b[2]);
            mma_bf16(acc[1][nb*2+1], a1, b[1], b[3]);
        }
    }
    #pragma unroll
    for (int mt = 0; mt < 2; mt++) {
        float sA = 0.f, sB = 0.f;
        #pragma unroll
        for (int j = 0; j < 8; j++) {
            sA += fexp(acc[mt][j][0]) + fexp(acc[mt][j][1]);
            sB += fexp(acc[mt][j][2]) + fexp(acc[mt][j][3]);
        }
        sA += __shfl_xor_sync(0xffffffffu, sA, 1);
        sA += __shfl_xor_sync(0xffffffffu, sA, 2);
        sB += __shfl_xor_sync(0xffffffffu, sB, 1);
        sB += __shfl_xor_sync(0xffffffffu, sB, 2);
        if ((lane & 3) == 0) {
            int row = rbase + m0 + mt*16 + (lane >> 2);
            atomicAdd(&g_sumexp[row], sA);
            atomicAdd(&g_sumexp[row + 8], sB);
        }
    }
}

// ---------------- final loss ---------------------------------------------------------
__global__ void loss_kernel(const int* __restrict__ tgt_lens, float* out) {
    int r = blockIdx.x*blockDim.x + threadIdx.x;
    if (r >= NROWS) return;
    int t = r / B_, b = r % B_;
    if (t < tgt_lens[b] - 1) {
        float nll = logf(g_sumexp[r]) - g_lbl[r];
        atomicAdd(out, nll);
    }
}

// ---------------- launch ----------------------------------------------------------------
extern "C" void kernel_launch(void* const* d_in, const int* in_sizes, int n_in,
                              void* d_out, int out_size) {
    const float* encoded   = (const float*)d_in[0];
    const float* enc_state = (const float*)d_in[1];
    const int*   tok       = (const int*)  d_in[2];
    const int*   enc_lens  = (const int*)  d_in[3];
    const int*   tgt_lens  = (const int*)  d_in[4];
    const float* E         = (const float*)d_in[5];
    const float* P         = (const float*)d_in[6];
    const float* W0        = (const float*)d_in[7];
    const float* U0        = (const float*)d_in[8];
    const float* b0        = (const float*)d_in[9];
    const float* W1        = (const float*)d_in[10];
    const float* U1        = (const float*)d_in[11];
    const float* b1        = (const float*)d_in[12];
    const float* Wo        = (const float*)d_in[13];
    const float* bo        = (const float*)d_in[14];
    float* out = (float*)d_out;

    static int s_attr_done = 0;
    if (!s_attr_done) {
        cudaFuncSetAttribute(step_loop,  cudaFuncAttributeMaxDynamicSharedMemorySize, SMEM_STEP);
        cudaFuncSetAttribute(embed_mma,  cudaFuncAttributeMaxDynamicSharedMemorySize, SMEM_EMB);
        cudaFuncSetAttribute(embw_mma,   cudaFuncAttributeMaxDynamicSharedMemorySize, SMEM_EMBW);
        cudaFuncSetAttribute(hproj_mma,  cudaFuncAttributeMaxDynamicSharedMemorySize, SMEM_HP);
        cudaFuncSetAttribute(tmp_mma,    cudaFuncAttributeMaxDynamicSharedMemorySize, SMEM_TP);
        cudaFuncSetAttribute(sumexp_mma, cudaFuncAttributeMaxDynamicSharedMemorySize, SMEM_SE);
        s_attr_done = 1;
    }

    reorder_w<<<(K0_*1024 + K1_*1024 + 255)/256, 256>>>(W0, U0, W1, U1);
    convert_lin<<<(CLT/4 + 255)/256, 256>>>(E, Wo, encoded);
    pt_convert<<<2*EMB_*RANK_/256, 256>>>(P);
    embed_mma<<<dim3(4, 12), 256, SMEM_EMB>>>(tok);
    embw_mma<<<dim3(32, 12), 256, SMEM_EMBW>>>();
    init_kernel<<<128, 256>>>(enc_state, out);

    step_loop<<<NBLK, 128, SMEM_STEP>>>(b0, b1, enc_lens);

    hproj_mma<<<dim3(8, 12), 256, SMEM_HP>>>(bo);
    tmp_mma<<<12, 256, SMEM_TP>>>();
    label_kernel<<<188, 256>>>(tok, E);
    sumexp_mma<<<dim3(250, 12), 256, SMEM_SE>>>();
    loss_kernel<<<6, 256>>>(tgt_lens, out);
}

// round 16
// speedup vs baseline: 1.0871x; 1.0102x over previous
#include <cuda_runtime.h>
#include <cuda_bf16.h>
#include <math.h>
#include <stdint.h>

#define S_     56
#define B_     32
#define C_     1024
#define T_     48
#define H_     1024
#define EMB_   512
#define RANK_  128
#define VOCAB_ 32000
#define TM1    47
#define NROWS  (TM1*B_)     /* 1504 */
#define NRPAD  1536
#define G4     (4*H_)       /* 4096 */
#define K0_    2560
#define KL_    2048         /* in-loop K for both gates */
#define K1_    2048
#define NBLK   256          /* persistent grid */
#define NSPLIT 4            /* k-splits */

// ---------------- scratch (device globals) ----------------------------------
__device__ __align__(16) __nv_bfloat16 g_W0b[K0_*G4];     // reordered col'=4u+g
__device__ __align__(16) __nv_bfloat16 g_W1b[K1_*G4];     // reordered
__device__ __align__(16) __nv_bfloat16 g_Eb[VOCAB_*RANK_];
__device__ __align__(16) __nv_bfloat16 g_WoB[2048*EMB_];
__device__ __align__(16) __nv_bfloat16 g_PbT[EMB_*RANK_]; // P^T, k-major [512][128]
__device__ __align__(16) __nv_bfloat16 g_Pb[RANK_*EMB_];  // P bf16 [128][512]
__device__ __align__(16) __nv_bfloat16 g_encB[S_*B_*C_];
__device__ __align__(16) __nv_bfloat16 g_embB[NRPAD*EMB_];
__device__ __align__(16) __nv_bfloat16 g_xa[2][B_*KL_];   // ping-pong [ctx|h0]
__device__ __align__(16) __nv_bfloat16 g_xb[2][B_*K1_];   // ping-pong [h0|h1]
__device__ __align__(16) __nv_bfloat16 g_featsB[NRPAD*2048];
__device__ __align__(16) __nv_bfloat16 g_hprojB[NRPAD*EMB_];
__device__ __align__(16) __nv_bfloat16 g_tmpB[NRPAD*RANK_];
__device__ float g_embW[(size_t)NRPAD*G4];                // emb @ W0emb (reordered)
__device__ float g_gates_part[NSPLIT][B_*G4];
__device__ float g_c0[B_*H_], g_c1[B_*H_];
__device__ float g_spart[8][B_*64];                       // partial attn scores
__device__ float g_tmp[NRPAD*RANK_];
__device__ float g_sumexp[NRPAD];

// persistent-kernel sync state
__device__ int g_bar_count = 0;
__device__ volatile int g_bar_gen = 0;

// ---------------- helpers ------------------------------------------------
__device__ __forceinline__ void ldsm_x4(uint32_t* r, const void* p) {
    uint32_t a = (uint32_t)__cvta_generic_to_shared(p);
    asm volatile("ldmatrix.sync.aligned.m8n8.x4.shared.b16 {%0,%1,%2,%3}, [%4];"
        : "=r"(r[0]), "=r"(r[1]), "=r"(r[2]), "=r"(r[3]) : "r"(a));
}
__device__ __forceinline__ void ldsm_x4_t(uint32_t* r, const void* p) {
    uint32_t a = (uint32_t)__cvta_generic_to_shared(p);
    asm volatile("ldmatrix.sync.aligned.m8n8.x4.trans.shared.b16 {%0,%1,%2,%3}, [%4];"
        : "=r"(r[0]), "=r"(r[1]), "=r"(r[2]), "=r"(r[3]) : "r"(a));
}
__device__ __forceinline__ void mma_bf16(float* d, const uint32_t* a, uint32_t b0, uint32_t b1) {
    asm volatile("mma.sync.aligned.m16n8k16.row.col.f32.bf16.bf16.f32 "
        "{%0,%1,%2,%3},{%4,%5,%6,%7},{%8,%9},{%0,%1,%2,%3};"
        : "+f"(d[0]), "+f"(d[1]), "+f"(d[2]), "+f"(d[3])
        : "r"(a[0]), "r"(a[1]), "r"(a[2]), "r"(a[3]), "r"(b0), "r"(b1));
}
__device__ __forceinline__ void cp16(void* s, const void* g) {
    uint32_t sa = (uint32_t)__cvta_generic_to_shared(s);
    asm volatile("cp.async.cg.shared.global [%0], [%1], 16;" :: "r"(sa), "l"(g));
}
__device__ __forceinline__ void cp_commit()  { asm volatile("cp.async.commit_group;"); }
__device__ __forceinline__ void cp_wait2()   { asm volatile("cp.async.wait_group 2;"); }
__device__ __forceinline__ void cp_waitall() { asm volatile("cp.async.wait_all;"); }

__device__ __forceinline__ float tanhfast(float x) {
    float r; asm("tanh.approx.f32 %0, %1;" : "=f"(r) : "f"(x)); return r;
}
__device__ __forceinline__ float sigf(float x) { return 0.5f*tanhfast(0.5f*x) + 0.5f; }

__device__ __forceinline__ float fexp(float x) {
    float y = x * 1.44269504088896341f;
    y = fminf(fmaxf(y, -120.f), 120.f);
    float n = rintf(y);
    float f = y - n;
    float p = 1.53386992e-4f;
    p = fmaf(p, f, 1.33938367e-3f);
    p = fmaf(p, f, 9.61843445e-3f);
    p = fmaf(p, f, 5.55041086e-2f);
    p = fmaf(p, f, 2.40226507e-1f);
    p = fmaf(p, f, 6.93147181e-1f);
    p = fmaf(p, f, 1.0f);
    int e = (int)n;
    return p * __int_as_float((e + 127) << 23);
}

// grid-wide flat barrier, nanosleep spin
__device__ __forceinline__ void gsync() {
    __syncthreads();
    if (threadIdx.x == 0) {
        __threadfence();
        int gen = g_bar_gen;
        if (atomicAdd(&g_bar_count, 1) == NBLK - 1) {
            g_bar_count = 0;
            __threadfence();
            g_bar_gen = gen + 1;
        } else {
            while (g_bar_gen == gen) __nanosleep(64);
        }
    }
    __syncthreads();
}

// ---------------- weight reorder (gates) + linear convert ----------------------
__global__ void reorder_w(const float* __restrict__ W0, const float* __restrict__ U0,
                          const float* __restrict__ W1, const float* __restrict__ U1) {
    int idx = blockIdx.x*256 + threadIdx.x;
    const int tot0 = K0_*1024;
    const int tot1 = K1_*1024;
    const float* src; __nv_bfloat16* d;
    int u;
    if (idx < tot0) {
        int k = idx >> 10; u = idx & 1023;
        src = (k < 1536) ? (W0 + (size_t)k*G4) : (U0 + (size_t)(k-1536)*G4);
        d = g_W0b + (size_t)k*G4 + u*4;
    } else if (idx < tot0 + tot1) {
        int j = idx - tot0;
        int k = j >> 10; u = j & 1023;
        src = (k < 1024) ? (W1 + (size_t)k*G4) : (U1 + (size_t)(k-1024)*G4);
        d = g_W1b + (size_t)k*G4 + u*4;
    } else return;
    __nv_bfloat162 p0(__float2bfloat16_rn(src[u]),        __float2bfloat16_rn(src[1024+u]));
    __nv_bfloat162 p1(__float2bfloat16_rn(src[2048+u]),   __float2bfloat16_rn(src[3072+u]));
    *(__nv_bfloat162*)(d)   = p0;
    *(__nv_bfloat162*)(d+2) = p1;
}

#define EE   (VOCAB_*RANK_)
#define WOE  (2048*EMB_)
#define ENCE (S_*B_*C_)
#define CLT  (EE + WOE + ENCE)
__global__ void convert_lin(const float* __restrict__ E, const float* __restrict__ Wo,
                            const float* __restrict__ enc) {
    long long i4 = ((long long)blockIdx.x*256 + threadIdx.x) * 4;
    if (i4 >= CLT) return;
    const float* src; __nv_bfloat16* dst;
    if (i4 < EE)            { src = E + i4;               dst = g_Eb  + i4; }
    else if (i4 < EE + WOE) { src = Wo + (i4-EE);         dst = g_WoB + (i4-EE); }
    else                    { src = enc + (i4-EE-WOE);    dst = g_encB + (i4-EE-WOE); }
    float4 v = *(const float4*)src;
    __nv_bfloat162* d2 = (__nv_bfloat162*)dst;
    d2[0] = __nv_bfloat162(__float2bfloat16_rn(v.x), __float2bfloat16_rn(v.y));
    d2[1] = __nv_bfloat162(__float2bfloat16_rn(v.z), __float2bfloat16_rn(v.w));
}

// P converts: g_PbT[k][c] = bf16(P[c][k]) ; g_Pb = bf16(P)
__global__ void pt_convert(const float* __restrict__ P) {
    int idx = blockIdx.x*256 + threadIdx.x;    // 131072
    if (idx < EMB_*RANK_) {
        int k = idx >> 7, c = idx & 127;
        g_PbT[k*RANK_ + c] = __float2bfloat16_rn(P[c*EMB_ + k]);
    } else {
        int j = idx - EMB_*RANK_;
        g_Pb[j] = __float2bfloat16_rn(P[j]);
    }
}

// ---------------- embedding via bf16 mma: 128x128 tiles ---------------------------
#define EMB_TS (128*136*2)      /* 34816 */
#define SMEM_EMB (2*EMB_TS)

__global__ void __launch_bounds__(256) embed_mma(const int* __restrict__ tok) {
    extern __shared__ __align__(16) char msm[];
    typedef __nv_bfloat16 TT[128][136];
    TT* ts = (TT*)msm;
    TT* ps = (TT*)(msm + EMB_TS);
    int tid = threadIdx.x, lane = tid & 31, w = tid >> 5;
    int cbase = blockIdx.x * 128;
    int rbase = blockIdx.y * 128;
    #pragma unroll
    for (int q = 0; q < 8; q++) {
        int c = tid + q*256;
        int row = c >> 4, kc = c & 15;
        int r = rbase + row;
        int t = r >> 5, b = r & 31;
        int token = (t < TM1) ? tok[b*T_ + t] : 0;
        cp16(&(*ts)[row][kc*8], g_Eb + (size_t)token*RANK_ + kc*8);
        cp16(&(*ps)[row][kc*8], g_Pb + (size_t)row*EMB_ + cbase + kc*8);
    }
    cp_commit();
    cp_waitall();
    __syncthreads();
    int m0 = (w & 3)*32, n0 = (w >> 2)*64;
    float acc[2][8][4] = {};
    #pragma unroll
    for (int ks = 0; ks < 8; ks++) {
        uint32_t a0[4], a1[4];
        ldsm_x4(a0, &(*ts)[m0 + (lane & 15)][ks*16 + (lane >> 4)*8]);
        ldsm_x4(a1, &(*ts)[m0 + 16 + (lane & 15)][ks*16 + (lane >> 4)*8]);
        #pragma unroll
        for (int nb = 0; nb < 4; nb++) {
            uint32_t b[4];
            ldsm_x4_t(b, &(*ps)[ks*16 + (lane & 15)][n0 + nb*16 + (lane >> 4)*8]);
            mma_bf16(acc[0][nb*2],   a0, b[0], b[1]);
            mma_bf16(acc[0][nb*2+1], a0, b[2], b[3]);
            mma_bf16(acc[1][nb*2],   a1, b[0], b[1]);
            mma_bf16(acc[1][nb*2+1], a1, b[2], b[3]);
        }
    }
    #pragma unroll
    for (int mt = 0; mt < 2; mt++)
        #pragma unroll
        for (int j = 0; j < 8; j++) {
            int col = cbase + n0 + j*8 + 2*(lane & 3);
            int r = rbase + m0 + mt*16 + (lane >> 2);
            __nv_bfloat162 o0(__float2bfloat16_rn(acc[mt][j][0]), __float2bfloat16_rn(acc[mt][j][1]));
            __nv_bfloat162 o1(__float2bfloat16_rn(acc[mt][j][2]), __float2bfloat16_rn(acc[mt][j][3]));
            *(__nv_bfloat162*)&g_embB[(size_t)r*EMB_ + col]     = o0;
            *(__nv_bfloat162*)&g_embB[(size_t)(r+8)*EMB_ + col] = o1;
        }
}

// ---------------- embW = embB @ W0b[0:512] (fp32 out), 128x128 tiles, 3-stage ------
#define EMBW_XS (3*128*72*2)    /* 55296 */
#define EMBW_WS (3*64*136*2)    /* 52224 */
#define SMEM_EMBW (EMBW_XS + EMBW_WS)

__global__ void __launch_bounds__(256) embw_mma() {
    extern __shared__ __align__(16) char esm[];
    typedef __nv_bfloat16 XT[128][72];
    typedef __nv_bfloat16 WT[64][136];
    XT* xs = (XT*)esm;
    WT* ws = (WT*)(esm + EMBW_XS);
    int tid = threadIdx.x, lane = tid & 31, w = tid >> 5;
    int cbase = blockIdx.x * 128;
    int rbase = blockIdx.y * 128;
    int m0 = (w & 3) * 32, n0 = (w >> 2) * 64;
    float acc[2][8][4] = {};

    auto load_chunk = [&](int ch) {
        int st = ch % 3; int kb = ch * 64;
        #pragma unroll
        for (int q = 0; q < 4; q++) {
            int c = tid + q*256;
            int row = c >> 3, kc = c & 7;
            cp16(&xs[st][row][kc*8], g_embB + (size_t)(rbase + row)*EMB_ + kb + kc*8);
        }
        #pragma unroll
        for (int q = 0; q < 4; q++) {
            int c = tid + q*256;
            int kr = c >> 4, cc = c & 15;
            cp16(&ws[st][kr][cc*8], g_W0b + (size_t)(kb + kr)*G4 + cbase + cc*8);
        }
    };
    load_chunk(0); cp_commit();
    load_chunk(1); cp_commit();
    for (int ch = 0; ch < 8; ch++) {
        asm volatile("cp.async.wait_group 1;");
        __syncthreads();
        if (ch + 2 < 8) load_chunk(ch + 2);
        cp_commit();
        int st = ch % 3;
        #pragma unroll
        for (int ks = 0; ks < 4; ks++) {
            uint32_t a0[4], a1[4];
            ldsm_x4(a0, &xs[st][m0 + (lane & 15)][ks*16 + (lane >> 4)*8]);
            ldsm_x4(a1, &xs[st][m0 + 16 + (lane & 15)][ks*16 + (lane >> 4)*8]);
            #pragma unroll
            for (int nb = 0; nb < 4; nb++) {
                uint32_t b[4];
                ldsm_x4_t(b, &ws[st][ks*16 + (lane & 15)][n0 + nb*16 + (lane >> 4)*8]);
                mma_bf16(acc[0][nb*2],   a0, b[0], b[1]);
                mma_bf16(acc[0][nb*2+1], a0, b[2], b[3]);
                mma_bf16(acc[1][nb*2],   a1, b[0], b[1]);
                mma_bf16(acc[1][nb*2+1], a1, b[2], b[3]);
            }
        }
        __syncthreads();
    }
    #pragma unroll
    for (int mt = 0; mt < 2; mt++)
        #pragma unroll
        for (int j = 0; j < 8; j++) {
            int col = cbase + n0 + j*8 + 2*(lane & 3);
            int r = rbase + m0 + mt*16 + (lane >> 2);
            *(float2*)&g_embW[(size_t)r*G4 + col]     = make_float2(acc[mt][j][0], acc[mt][j][1]);
            *(float2*)&g_embW[(size_t)(r+8)*G4 + col] = make_float2(acc[mt][j][2], acc[mt][j][3]);
        }
}

// ---------------- init ----------------------------------------------------------
__global__ void init_kernel(const float* __restrict__ enc_state, float* out) {
    int i = blockIdx.x * blockDim.x + threadIdx.x;   // 32768
    if (i < B_*H_) {
        int b = i >> 10, j = i & 1023;
        float h0v = enc_state[i];
        float h1v = enc_state[B_*H_ + i];
        g_c0[i] = 0.f; g_c1[i] = 0.f;
        __nv_bfloat16 h0b = __float2bfloat16_rn(h0v);
        __nv_bfloat16 h1b = __float2bfloat16_rn(h1v);
        g_xb[0][b*K1_ + j]        = h0b;
        g_xb[0][b*K1_ + 1024 + j] = h1b;
        g_xa[0][b*KL_ + 1024 + j] = h0b;
        g_xa[0][b*KL_ + j]        = __float2bfloat16_rn(0.f);   // ctx = 0
    }
    {
        __nv_bfloat162 z(__float2bfloat16_rn(0.f), __float2bfloat16_rn(0.f));
        *(__nv_bfloat162*)&g_featsB[(size_t)NROWS*2048 + i*2] = z;
    }
    if (i < NRPAD) g_sumexp[i] = 0.f;
    if (i == 0) { g_bar_count = 0; g_bar_gen = 0; out[0] = 0.f; }
}

// ================= persistent step loop (R8/R13 structure — best) ==================
#define XS_BYTES (4*32*72*2)
#define WS_BYTES (4*64*72*2)
#define SMEM_STEP (XS_BYTES + WS_BYTES)

// gates GEMM (K=2048, k-split 4, chunks of 64, depth-3 pipeline)
template<int WHICH>
__device__ void gates_phase(char* sraw, int bid, int p) {
    constexpr int NCH = 8;
    typedef __nv_bfloat16 XsT[32][72];
    typedef __nv_bfloat16 WsT[64][72];
    XsT* xs = (XsT*)sraw;
    WsT* ws = (WsT*)(sraw + XS_BYTES);
    const __nv_bfloat16* __restrict__ X = WHICH ? g_xb[p] : g_xa[p];
    const __nv_bfloat16* __restrict__ W = WHICH ? g_W1b : (g_W0b + (size_t)512*G4);
    int tid = threadIdx.x, lane = tid & 31, w = tid >> 5;
    int ctile  = bid & 63;
    int ksplit = bid >> 6;
    int cbase  = ctile * 64;
    int kstart = ksplit * 512;
    int n0 = w * 16;
    float acc[2][2][4] = {};

    auto load_chunk = [&](int ch) {
        int st = ch & 3; int kb = kstart + ch*64;
        #pragma unroll
        for (int q = 0; q < 2; q++) {
            int c = tid*2 + q;
            int row = c >> 3, kc = c & 7;
            cp16(&xs[st][row][kc*8], X + row*KL_ + kb + kc*8);
        }
        #pragma unroll
        for (int q = 0; q < 4; q++) {
            int c = tid + q*128;
            int row = c >> 3, cc = c & 7;
            cp16(&ws[st][row][cc*8], W + (size_t)(kb + row)*G4 + cbase + cc*8);
        }
    };
    load_chunk(0); cp_commit();
    load_chunk(1); cp_commit();
    load_chunk(2); cp_commit();
    for (int ch = 0; ch < NCH; ch++) {
        cp_wait2();
        __syncthreads();
        if (ch + 3 < NCH) load_chunk(ch + 3);
        cp_commit();
        int st = ch & 3;
        #pragma unroll
        for (int ks = 0; ks < 4; ks++) {
            uint32_t a0[4], a1[4], b[4];
            ldsm_x4(a0, &xs[st][(lane & 15)][ks*16 + (lane >> 4)*8]);
            ldsm_x4(a1, &xs[st][16 + (lane & 15)][ks*16 + (lane >> 4)*8]);
            ldsm_x4_t(b, &ws[st][ks*16 + (lane & 15)][n0 + (lane >> 4)*8]);
            mma_bf16(acc[0][0], a0, b[0], b[1]);
            mma_bf16(acc[0][1], a0, b[2], b[3]);
            mma_bf16(acc[1][0], a1, b[0], b[1]);
            mma_bf16(acc[1][1], a1, b[2], b[3]);
        }
    }
    cp_waitall();
    float* gp = g_gates_part[ksplit];
    #pragma unroll
    for (int mt = 0; mt < 2; mt++)
        #pragma unroll
        for (int nt = 0; nt < 2; nt++) {
            int row = mt*16 + (lane >> 2);
            int col = cbase + n0 + nt*8 + 2*(lane & 3);
            *(float2*)&gp[(size_t)row*G4 + col]     = make_float2(acc[mt][nt][0], acc[mt][nt][1]);
            *(float2*)&gp[(size_t)(row+8)*G4 + col] = make_float2(acc[mt][nt][2], acc[mt][nt][3]);
        }
}

// cell0: 256 blocks, each (b = bid&31, 128-unit slice)
__device__ void cell0_phase(int bid, int t, int p, const float* __restrict__ bias) {
    int b  = bid & 31;
    int u  = (bid >> 5)*128 + threadIdx.x;
    float4 ev = *(const float4*)&g_embW[((size_t)(t*B_ + b))*G4 + 4*u];
    float gi = bias[u]        + ev.x;
    float gf = bias[1024 + u] + ev.y;
    float gg = bias[2048 + u] + ev.z;
    float go = bias[3072 + u] + ev.w;
    #pragma unroll
    for (int pt = 0; pt < NSPLIT; pt++) {
        float4 gv = __ldcg((const float4*)&g_gates_part[pt][(size_t)b*G4 + 4*u]);
        gi += gv.x; gf += gv.y; gg += gv.z; go += gv.w;
    }
    float c = g_c0[b*H_ + u];
    float cn = sigf(gf)*c + sigf(gi)*tanhfast(gg);
    float hn = sigf(go)*tanhfast(cn);
    g_c0[b*H_ + u] = cn;
    __nv_bfloat16 hb = __float2bfloat16_rn(hn);
    g_xb[p][b*K1_ + u] = hb;                 // gates1 input this step
    g_xa[1-p][b*KL_ + 1024 + u] = hb;        // h0 next step
}

// cell1 + partial attention scores: 256 blocks, (b = bid>>3, 128-unit slice)
__device__ void cell1_phase(float* hs, int bid, int t, int p,
                            const float* __restrict__ bias,
                            const int* __restrict__ enc_lens) {
    int b     = bid >> 3;
    int slice = bid & 7;
    int tid = threadIdx.x;
    {
        int u = slice*128 + tid;
        float gi = bias[u], gf = bias[1024+u], gg = bias[2048+u], go = bias[3072+u];
        #pragma unroll
        for (int pt = 0; pt < NSPLIT; pt++) {
            float4 gv = __ldcg((const float4*)&g_gates_part[pt][(size_t)b*G4 + 4*u]);
            gi += gv.x; gf += gv.y; gg += gv.z; go += gv.w;
        }
        float c = g_c1[b*H_ + u];
        float cn = sigf(gf)*c + sigf(gi)*tanhfast(gg);
        float hn = sigf(go)*tanhfast(cn);
        g_c1[b*H_ + u] = cn;
        __nv_bfloat16 hb = __float2bfloat16_rn(hn);
        g_xb[1-p][b*K1_ + 1024 + u] = hb;          // h1 next step
        g_featsB[(size_t)(t*B_ + b)*2048 + u] = hb;
        hs[tid] = hn;
    }
    __syncthreads();
    int w = tid >> 5, lane = tid & 31;
    int len = enc_lens[b];
    #pragma unroll
    for (int i = 0; i < 14; i++) {
        int s = w*14 + i;
        if (s < len) {
            const __nv_bfloat16* e = g_encB + ((size_t)(s*B_ + b) << 10) + slice*128;
            uint2 v = *(const uint2*)(e + lane*4);
            const __nv_bfloat162* p2 = (const __nv_bfloat162*)&v;
            float2 f0 = __bfloat1622float2(p2[0]);
            float2 f1 = __bfloat1622float2(p2[1]);
            float a = f0.x*hs[lane*4] + f0.y*hs[lane*4+1]
                    + f1.x*hs[lane*4+2] + f1.y*hs[lane*4+3];
            #pragma unroll
            for (int o = 16; o; o >>= 1) a += __shfl_xor_sync(0xffffffffu, a, o);
            if (lane == 0) g_spart[slice][b*64 + s] = a;
        }
    }
}

// attention finish: softmax + ctx, 256 blocks, (b = bid>>3, 128-col slice)
__device__ void attn_fin(float* sc, int bid, int t, int p,
                         const int* __restrict__ enc_lens) {
    int b  = bid >> 3;
    int c0 = (bid & 7)*128;
    int tid = threadIdx.x;
    int len = enc_lens[b];
    if (tid < 64) {
        float v = -1.0e30f;
        if (tid < len) {
            v = 0.f;
            #pragma unroll
            for (int k = 0; k < 8; k++) v += __ldcg(&g_spart[k][b*64 + tid]);
        }
        sc[tid] = v;
    }
    __syncthreads();
    if (tid < 32) {
        int lane = tid;
        float v0 = sc[lane];
        float v1 = (lane + 32 < S_) ? sc[lane + 32] : -1.0e30f;
        float m = fmaxf(v0, v1);
        #pragma unroll
        for (int o = 16; o; o >>= 1) m = fmaxf(m, __shfl_xor_sync(0xffffffffu, m, o));
        float e0 = __expf(v0 - m);
        float e1 = (lane + 32 < S_) ? __expf(v1 - m) : 0.f;
        float sum = e0 + e1;
        #pragma unroll
        for (int o = 16; o; o >>= 1) sum += __shfl_xor_sync(0xffffffffu, sum, o);
        sc[lane] = e0 / sum;
        if (lane + 32 < S_) sc[lane + 32] = e1 / sum;
    }
    __syncthreads();
    int col = c0 + tid;
    float a = 0.f;
    #pragma unroll 8
    for (int s = 0; s < S_; s++)
        a = fmaf(sc[s], __bfloat162float(g_encB[((size_t)(s*B_ + b) << 10) + col]), a);
    __nv_bfloat16 ab = __float2bfloat16_rn(a);
    g_featsB[(size_t)(t*B_ + b)*2048 + 1024 + col] = ab;
    g_xa[1-p][b*KL_ + col] = ab;              // ctx next step
}

__global__ void __launch_bounds__(128, 2) step_loop(const float* __restrict__ b0,
                                                    const float* __restrict__ b1,
                                                    const int* __restrict__ enc_lens) {
    extern __shared__ __align__(16) char sraw[];
    __shared__ float s_hs[128];
    __shared__ float s_sc[64];
    int bid = blockIdx.x;
    for (int t = 0; t < TM1; t++) {
        int p = t & 1;
        gates_phase<0>(sraw, bid, p);
        gsync();
        cell0_phase(bid, t, p, b0);
        gsync();
        gates_phase<1>(sraw, bid, p);
        gsync();
        cell1_phase(s_hs, bid, t, p, b1, enc_lens);
        gsync();
        attn_fin(s_sc, bid, t, p, enc_lens);
        gsync();
    }
}

// ---------------- hproj = tanh(featsB @ WoB + bo), 128x64 tiles, bf16 out ----------
#define HP_XS (3*128*72*2)    /* 55296 */
#define HP_WS (3*64*72*2)     /* 27648 */
#define SMEM_HP (HP_XS + HP_WS)

__global__ void __launch_bounds__(256) hproj_mma(const float* __restrict__ bo) {
    extern __shared__ __align__(16) char hsm[];
    typedef __nv_bfloat16 XT[128][72];
    typedef __nv_bfloat16 WT[64][72];
    XT* xs = (XT*)hsm;
    WT* ws = (WT*)(hsm + HP_XS);
    int tid = threadIdx.x, lane = tid & 31, w = tid >> 5;
    int cbase = blockIdx.x * 64;
    int rbase = blockIdx.y * 128;
    int m0 = (w & 3) * 32, n0 = (w >> 2) * 32;
    float acc[2][4][4] = {};

    auto load_chunk = [&](int ch) {
        int st = ch % 3; int kb = ch * 64;
        #pragma unroll
        for (int q = 0; q < 4; q++) {
            int c = tid + q*256;
            int row = c >> 3, kc = c & 7;
            cp16(&xs[st][row][kc*8], g_featsB + (size_t)(rbase + row)*2048 + kb + kc*8);
        }
        #pragma unroll
        for (int q = 0; q < 2; q++) {
            int c = tid + q*256;
            int kr = c >> 3, cc = c & 7;
            cp16(&ws[st][kr][cc*8], g_WoB + (size_t)(kb + kr)*EMB_ + cbase + cc*8);
        }
    };
    load_chunk(0); cp_commit();
    load_chunk(1); cp_commit();
    for (int ch = 0; ch < 32; ch++) {
        asm volatile("cp.async.wait_group 1;");
        __syncthreads();
        if (ch + 2 < 32) load_chunk(ch + 2);
        cp_commit();
        int st = ch % 3;
        #pragma unroll
        for (int ks = 0; ks < 4; ks++) {
            uint32_t a0[4], a1[4];
            ldsm_x4(a0, &xs[st][m0 + (lane & 15)][ks*16 + (lane >> 4)*8]);
            ldsm_x4(a1, &xs[st][m0 + 16 + (lane & 15)][ks*16 + (lane >> 4)*8]);
            #pragma unroll
            for (int nb = 0; nb < 2; nb++) {
                uint32_t b[4];
                ldsm_x4_t(b, &ws[st][ks*16 + (lane & 15)][n0 + nb*16 + (lane >> 4)*8]);
                mma_bf16(acc[0][nb*2],   a0, b[0], b[1]);
                mma_bf16(acc[0][nb*2+1], a0, b[2], b[3]);
                mma_bf16(acc[1][nb*2],   a1, b[0], b[1]);
                mma_bf16(acc[1][nb*2+1], a1, b[2], b[3]);
            }
        }
        __syncthreads();
    }
    #pragma unroll
    for (int mt = 0; mt < 2; mt++)
        #pragma unroll
        for (int j = 0; j < 4; j++) {
            int col = cbase + n0 + j*8 + 2*(lane & 3);
            float b0v = bo[col], b1v = bo[col+1];
            int r = rbase + m0 + mt*16 + (lane >> 2);
            __nv_bfloat162 o0(__float2bfloat16_rn(tanhf(acc[mt][j][0] + b0v)),
                              __float2bfloat16_rn(tanhf(acc[mt][j][1] + b1v)));
            __nv_bfloat162 o1(__float2bfloat16_rn(tanhf(acc[mt][j][2] + b0v)),
                              __float2bfloat16_rn(tanhf(acc[mt][j][3] + b1v)));
            *(__nv_bfloat162*)&g_hprojB[(size_t)r*EMB_ + col]     = o0;
            *(__nv_bfloat162*)&g_hprojB[(size_t)(r+8)*EMB_ + col] = o1;
        }
}

// ---------------- tmp = hprojB @ PbT (128x128 tiles, fp32+bf16 out) ----------------
#define TP_XS (3*128*72*2)    /* 55296 */
#define TP_WS (3*64*136*2)    /* 52224 */
#define SMEM_TP (TP_XS + TP_WS)

__global__ void __launch_bounds__(256) tmp_mma() {
    extern __shared__ __align__(16) char tsm[];
    typedef __nv_bfloat16 XT[128][72];
    typedef __nv_bfloat16 WT[64][136];
    XT* xs = (XT*)tsm;
    WT* ws = (WT*)(tsm + TP_XS);
    int tid = threadIdx.x, lane = tid & 31, w = tid >> 5;
    int rbase = blockIdx.x * 128;
    int m0 = (w & 3) * 32, n0 = (w >> 2) * 64;
    float acc[2][8][4] = {};

    auto load_chunk = [&](int ch) {
        int st = ch % 3; int kb = ch * 64;
        #pragma unroll
        for (int q = 0; q < 4; q++) {
            int c = tid + q*256;
            int row = c >> 3, kc = c & 7;
            cp16(&xs[st][row][kc*8], g_hprojB + (size_t)(rbase + row)*EMB_ + kb + kc*8);
        }
        #pragma unroll
        for (int q = 0; q < 4; q++) {
            int c = tid + q*256;
            int kr = c >> 4, cc = c & 15;
            cp16(&ws[st][kr][cc*8], g_PbT + (size_t)(kb + kr)*RANK_ + cc*8);
        }
    };
    load_chunk(0); cp_commit();
    load_chunk(1); cp_commit();
    for (int ch = 0; ch < 8; ch++) {
        asm volatile("cp.async.wait_group 1;");
        __syncthreads();
        if (ch + 2 < 8) load_chunk(ch + 2);
        cp_commit();
        int st = ch % 3;
        #pragma unroll
        for (int ks = 0; ks < 4; ks++) {
            uint32_t a0[4], a1[4];
            ldsm_x4(a0, &xs[st][m0 + (lane & 15)][ks*16 + (lane >> 4)*8]);
            ldsm_x4(a1, &xs[st][m0 + 16 + (lane & 15)][ks*16 + (lane >> 4)*8]);
            #pragma unroll
            for (int nb = 0; nb < 4; nb++) {
                uint32_t b[4];
                ldsm_x4_t(b, &ws[st][ks*16 + (lane & 15)][n0 + nb*16 + (lane >> 4)*8]);
                mma_bf16(acc[0][nb*2],   a0, b[0], b[1]);
                mma_bf16(acc[0][nb*2+1], a0, b[2], b[3]);
                mma_bf16(acc[1][nb*2],   a1, b[0], b[1]);
                mma_bf16(acc[1][nb*2+1], a1, b[2], b[3]);
            }
        }
        __syncthreads();
    }
    #pragma unroll
    for (int mt = 0; mt < 2; mt++)
        #pragma unroll
        for (int j = 0; j < 8; j++) {
            int col = n0 + j*8 + 2*(lane & 3);
            int r = rbase + m0 + mt*16 + (lane >> 2);
            *(float2*)&g_tmp[(size_t)r*RANK_ + col]     = make_float2(acc[mt][j][0], acc[mt][j][1]);
            *(float2*)&g_tmp[(size_t)(r+8)*RANK_ + col] = make_float2(acc[mt][j][2], acc[mt][j][3]);
            __nv_bfloat162 t0(__float2bfloat16_rn(acc[mt][j][0]), __float2bfloat16_rn(acc[mt][j][1]));
            __nv_bfloat162 t1(__float2bfloat16_rn(acc[mt][j][2]), __float2bfloat16_rn(acc[mt][j][3]));
            *(__nv_bfloat162*)&g_tmpB[(size_t)r*RANK_ + col]     = t0;
            *(__nv_bfloat162*)&g_tmpB[(size_t)(r+8)*RANK_ + col] = t1;
        }
}

// ---------------- sumexp via bf16 mma: 128 rows x 128 vocab per block ----------------
#define SE_TS (128*136*2)       /* 34816 */
#define SMEM_SE (2*SE_TS)

__global__ void __launch_bounds__(256) sumexp_mma() {
    extern __shared__ __align__(16) char ssm[];
    typedef __nv_bfloat16 TT[128][136];
    TT* ts = (TT*)ssm;
    TT* es = (TT*)(ssm + SE_TS);
    int tid = threadIdx.x, lane = tid & 31, w = tid >> 5;
    int vbase = blockIdx.x * 128, rbase = blockIdx.y * 128;
    #pragma unroll
    for (int q = 0; q < 8; q++) {
        int c = tid + q*256;
        int row = c >> 4, kc = c & 15;
        *(uint4*)&(*ts)[row][kc*8] = *(const uint4*)&g_tmpB[(size_t)(rbase + row)*RANK_ + kc*8];
        *(uint4*)&(*es)[row][kc*8] = *(const uint4*)&g_Eb[(size_t)(vbase + row)*RANK_ + kc*8];
    }
    __syncthreads();
    int m0 = (w & 3)*32, n0 = (w >> 2)*64;
    float acc[2][8][4] = {};
    #pragma unroll
    for (int ks = 0; ks < 8; ks++) {
        uint32_t a0[4], a1[4];
        ldsm_x4(a0, &(*ts)[m0 + (lane & 15)][ks*16 + (lane >> 4)*8]);
        ldsm_x4(a1, &(*ts)[m0 + 16 + (lane & 15)][ks*16 + (lane >> 4)*8]);
        #pragma unroll
        for (int nb = 0; nb < 4; nb++) {
            uint32_t b[4];
            ldsm_x4(b, &(*es)[n0 + nb*16 + (lane & 15)][ks*16 + (lane >> 4)*8]);
            mma_bf16(acc[0][nb*2],   a0, b[0], b[2]);
            mma_bf16(acc[0][nb*2+1], a0, b[1], b[3]);
            mma_bf16(acc[1][nb*2],   a1, b[0], b[2]);
            mma_bf16(acc[1][nb*2+1], a1, b[1], b[3]);
        }
    }
    #pragma unroll
    for (int mt = 0; mt < 2; mt++) {
        float sA = 0.f, sB = 0.f;
        #pragma unroll
        for (int j = 0; j < 8; j++) {
            sA += fexp(acc[mt][j][0]) + fexp(acc[mt][j][1]);
            sB += fexp(acc[mt][j][2]) + fexp(acc[mt][j][3]);
        }
        sA += __shfl_xor_sync(0xffffffffu, sA, 1);
        sA += __shfl_xor_sync(0xffffffffu, sA, 2);
        sB += __shfl_xor_sync(0xffffffffu, sB, 1);
        sB += __shfl_xor_sync(0xffffffffu, sB, 2);
        if ((lane & 3) == 0) {
            int row = rbase + m0 + mt*16 + (lane >> 2);
            atomicAdd(&g_sumexp[row], sA);
            atomicAdd(&g_sumexp[row + 8], sB);
        }
    }
}

// ---------------- label logit + loss (merged; runs after sumexp) -----------------------
__global__ void label_loss_kernel(const int* __restrict__ tok, const float* __restrict__ E,
                                  const int* __restrict__ tgt_lens, float* out) {
    int r = blockIdx.x*8 + (threadIdx.x >> 5);
    if (r >= NROWS) return;
    int lane = threadIdx.x & 31;
    int t = r / B_, b = r % B_;
    int lbl = tok[b*T_ + t + 1];
    float a = 0.f;
    for (int e = lane; e < RANK_; e += 32)
        a += g_tmp[(size_t)r*RANK_ + e] * E[(size_t)lbl*RANK_ + e];
    #pragma unroll
    for (int o = 16; o; o >>= 1) a += __shfl_xor_sync(0xffffffffu, a, o);
    if (lane == 0 && t < tgt_lens[b] - 1) {
        float nll = logf(g_sumexp[r]) - a;
        atomicAdd(out, nll);
    }
}

// ---------------- launch ----------------------------------------------------------------
extern "C" void kernel_launch(void* const* d_in, const int* in_sizes, int n_in,
                              void* d_out, int out_size) {
    const float* encoded   = (const float*)d_in[0];
    const float* enc_state = (const float*)d_in[1];
    const int*   tok       = (const int*)  d_in[2];
    const int*   enc_lens  = (const int*)  d_in[3];
    const int*   tgt_lens  = (const int*)  d_in[4];
    const float* E         = (const float*)d_in[5];
    const float* P         = (const float*)d_in[6];
    const float* W0        = (const float*)d_in[7];
    const float* U0        = (const float*)d_in[8];
    const float* b0        = (const float*)d_in[9];
    const float* W1        = (const float*)d_in[10];
    const float* U1        = (const float*)d_in[11];
    const float* b1        = (const float*)d_in[12];
    const float* Wo        = (const float*)d_in[13];
    const float* bo        = (const float*)d_in[14];
    float* out = (float*)d_out;

    static int s_attr_done = 0;
    if (!s_attr_done) {
        cudaFuncSetAttribute(step_loop,  cudaFuncAttributeMaxDynamicSharedMemorySize, SMEM_STEP);
        cudaFuncSetAttribute(embed_mma,  cudaFuncAttributeMaxDynamicSharedMemorySize, SMEM_EMB);
        cudaFuncSetAttribute(embw_mma,   cudaFuncAttributeMaxDynamicSharedMemorySize, SMEM_EMBW);
        cudaFuncSetAttribute(hproj_mma,  cudaFuncAttributeMaxDynamicSharedMemorySize, SMEM_HP);
        cudaFuncSetAttribute(tmp_mma,    cudaFuncAttributeMaxDynamicSharedMemorySize, SMEM_TP);
        cudaFuncSetAttribute(sumexp_mma, cudaFuncAttributeMaxDynamicSharedMemorySize, SMEM_SE);
        s_attr_done = 1;
    }

    reorder_w<<<(K0_*1024 + K1_*1024 + 255)/256, 256>>>(W0, U0, W1, U1);
    convert_lin<<<(CLT/4 + 255)/256, 256>>>(E, Wo, encoded);
    pt_convert<<<2*EMB_*RANK_/256, 256>>>(P);
    embed_mma<<<dim3(4, 12), 256, SMEM_EMB>>>(tok);
    embw_mma<<<dim3(32, 12), 256, SMEM_EMBW>>>();
    init_kernel<<<128, 256>>>(enc_state, out);

    step_loop<<<NBLK, 128, SMEM_STEP>>>(b0, b1, enc_lens);

    hproj_mma<<<dim3(8, 12), 256, SMEM_HP>>>(bo);
    tmp_mma<<<12, 256, SMEM_TP>>>();
    sumexp_mma<<<dim3(250, 12), 256, SMEM_SE>>>();
    label_loss_kernel<<<188, 256>>>(tok, E, tgt_lens, out);
}

// round 17
// speedup vs baseline: 1.0954x; 1.0076x over previous
#include <cuda_runtime.h>
#include <cuda_bf16.h>
#include <math.h>
#include <stdint.h>

#define S_     56
#define B_     32
#define C_     1024
#define T_     48
#define H_     1024
#define EMB_   512
#define RANK_  128
#define VOCAB_ 32000
#define TM1    47
#define NROWS  (TM1*B_)     /* 1504 */
#define NRPAD  1536
#define G4     (4*H_)       /* 4096 */
#define K0_    2560
#define KL_    2048         /* in-loop K for both gates */
#define K1_    2048
#define NBLK   256          /* persistent grid */
#define NSPLIT 4            /* k-splits */

// ---------------- scratch (device globals) ----------------------------------
__device__ __align__(16) __nv_bfloat16 g_W0b[K0_*G4];     // reordered col'=4u+g
__device__ __align__(16) __nv_bfloat16 g_W1b[K1_*G4];     // reordered
__device__ __align__(16) __nv_bfloat16 g_Eb[VOCAB_*RANK_];
__device__ __align__(16) __nv_bfloat16 g_WoB[2048*EMB_];
__device__ __align__(16) __nv_bfloat16 g_PbT[EMB_*RANK_]; // P^T, k-major [512][128]
__device__ __align__(16) __nv_bfloat16 g_Pb[RANK_*EMB_];  // P bf16 [128][512]
__device__ __align__(16) __nv_bfloat16 g_encB[S_*B_*C_];
__device__ __align__(16) __nv_bfloat16 g_embB[NRPAD*EMB_];
__device__ __align__(16) __nv_bfloat16 g_xa[2][B_*KL_];   // ping-pong [ctx|h0]
__device__ __align__(16) __nv_bfloat16 g_xb[2][B_*K1_];   // ping-pong [h0|h1]
__device__ __align__(16) __nv_bfloat16 g_featsB[NRPAD*2048];
__device__ __align__(16) __nv_bfloat16 g_hprojB[NRPAD*EMB_];
__device__ __align__(16) __nv_bfloat16 g_tmpB[NRPAD*RANK_];
__device__ float g_embW[(size_t)NRPAD*G4];                // emb @ W0emb (reordered)
__device__ float g_gates_part[NSPLIT][B_*G4];
__device__ float g_c0[B_*H_], g_c1[B_*H_];
__device__ float g_spart[8][B_*64];                       // partial attn scores
__device__ float g_tmp[NRPAD*RANK_];
__device__ float g_sumexp[NRPAD];

// persistent-kernel sync state
__device__ int g_bar_count = 0;
__device__ volatile int g_bar_gen = 0;

// ---------------- helpers ------------------------------------------------
__device__ __forceinline__ void ldsm_x4(uint32_t* r, const void* p) {
    uint32_t a = (uint32_t)__cvta_generic_to_shared(p);
    asm volatile("ldmatrix.sync.aligned.m8n8.x4.shared.b16 {%0,%1,%2,%3}, [%4];"
        : "=r"(r[0]), "=r"(r[1]), "=r"(r[2]), "=r"(r[3]) : "r"(a));
}
__device__ __forceinline__ void ldsm_x4_t(uint32_t* r, const void* p) {
    uint32_t a = (uint32_t)__cvta_generic_to_shared(p);
    asm volatile("ldmatrix.sync.aligned.m8n8.x4.trans.shared.b16 {%0,%1,%2,%3}, [%4];"
        : "=r"(r[0]), "=r"(r[1]), "=r"(r[2]), "=r"(r[3]) : "r"(a));
}
__device__ __forceinline__ void mma_bf16(float* d, const uint32_t* a, uint32_t b0, uint32_t b1) {
    asm volatile("mma.sync.aligned.m16n8k16.row.col.f32.bf16.bf16.f32 "
        "{%0,%1,%2,%3},{%4,%5,%6,%7},{%8,%9},{%0,%1,%2,%3};"
        : "+f"(d[0]), "+f"(d[1]), "+f"(d[2]), "+f"(d[3])
        : "r"(a[0]), "r"(a[1]), "r"(a[2]), "r"(a[3]), "r"(b0), "r"(b1));
}
__device__ __forceinline__ void cp16(void* s, const void* g) {
    uint32_t sa = (uint32_t)__cvta_generic_to_shared(s);
    asm volatile("cp.async.cg.shared.global [%0], [%1], 16;" :: "r"(sa), "l"(g));
}
__device__ __forceinline__ void cp_commit()  { asm volatile("cp.async.commit_group;"); }
__device__ __forceinline__ void cp_wait2()   { asm volatile("cp.async.wait_group 2;"); }
__device__ __forceinline__ void cp_waitall() { asm volatile("cp.async.wait_all;"); }

__device__ __forceinline__ float tanhfast(float x) {
    float r; asm("tanh.approx.f32 %0, %1;" : "=f"(r) : "f"(x)); return r;
}
__device__ __forceinline__ float sigf(float x) { return 0.5f*tanhfast(0.5f*x) + 0.5f; }

__device__ __forceinline__ float fexp(float x) {
    float y = x * 1.44269504088896341f;
    y = fminf(fmaxf(y, -120.f), 120.f);
    float n = rintf(y);
    float f = y - n;
    float p = 1.53386992e-4f;
    p = fmaf(p, f, 1.33938367e-3f);
    p = fmaf(p, f, 9.61843445e-3f);
    p = fmaf(p, f, 5.55041086e-2f);
    p = fmaf(p, f, 2.40226507e-1f);
    p = fmaf(p, f, 6.93147181e-1f);
    p = fmaf(p, f, 1.0f);
    int e = (int)n;
    return p * __int_as_float((e + 127) << 23);
}

// grid-wide flat barrier, nanosleep spin
__device__ __forceinline__ void gsync() {
    __syncthreads();
    if (threadIdx.x == 0) {
        __threadfence();
        int gen = g_bar_gen;
        if (atomicAdd(&g_bar_count, 1) == NBLK - 1) {
            g_bar_count = 0;
            __threadfence();
            g_bar_gen = gen + 1;
        } else {
            while (g_bar_gen == gen) __nanosleep(64);
        }
    }
    __syncthreads();
}

// ---------------- fused setup: reorder + convert + P + init --------------------
#define EE   (VOCAB_*RANK_)
#define WOE  (2048*EMB_)
#define ENCE (S_*B_*C_)
#define CLT  (EE + WOE + ENCE)
#define NB_REO  ((K0_*1024 + K1_*1024)/256)   /* 18432 */
#define NB_CONV (CLT/4/256)                    /* 6816  */
#define NB_PT   (2*EMB_*RANK_/256)             /* 512   */
#define NB_INIT 128
#define NB_SETUP (NB_REO + NB_CONV + NB_PT + NB_INIT)

__global__ void mega_setup(const float* __restrict__ W0, const float* __restrict__ U0,
                           const float* __restrict__ W1, const float* __restrict__ U1,
                           const float* __restrict__ E,  const float* __restrict__ Wo,
                           const float* __restrict__ enc, const float* __restrict__ P,
                           const float* __restrict__ enc_state, float* out) {
    int bb = blockIdx.x;
    int tid = threadIdx.x;
    if (bb < NB_REO) {
        // ---- gates weight reorder: new col' = 4*unit + gate
        int idx = bb*256 + tid;
        const int tot0 = K0_*1024;
        const float* src; __nv_bfloat16* d;
        int u;
        if (idx < tot0) {
            int k = idx >> 10; u = idx & 1023;
            src = (k < 1536) ? (W0 + (size_t)k*G4) : (U0 + (size_t)(k-1536)*G4);
            d = g_W0b + (size_t)k*G4 + u*4;
        } else {
            int j = idx - tot0;
            int k = j >> 10; u = j & 1023;
            src = (k < 1024) ? (W1 + (size_t)k*G4) : (U1 + (size_t)(k-1024)*G4);
            d = g_W1b + (size_t)k*G4 + u*4;
        }
        __nv_bfloat162 p0(__float2bfloat16_rn(src[u]),      __float2bfloat16_rn(src[1024+u]));
        __nv_bfloat162 p1(__float2bfloat16_rn(src[2048+u]), __float2bfloat16_rn(src[3072+u]));
        *(__nv_bfloat162*)(d)   = p0;
        *(__nv_bfloat162*)(d+2) = p1;
    } else if (bb < NB_REO + NB_CONV) {
        // ---- linear fp32 -> bf16 conversions (E, Wo, enc)
        long long i4 = ((long long)(bb - NB_REO)*256 + tid) * 4;
        const float* src; __nv_bfloat16* dst;
        if (i4 < EE)            { src = E + i4;               dst = g_Eb  + i4; }
        else if (i4 < EE + WOE) { src = Wo + (i4-EE);         dst = g_WoB + (i4-EE); }
        else                    { src = enc + (i4-EE-WOE);    dst = g_encB + (i4-EE-WOE); }
        float4 v = *(const float4*)src;
        __nv_bfloat162* d2 = (__nv_bfloat162*)dst;
        d2[0] = __nv_bfloat162(__float2bfloat16_rn(v.x), __float2bfloat16_rn(v.y));
        d2[1] = __nv_bfloat162(__float2bfloat16_rn(v.z), __float2bfloat16_rn(v.w));
    } else if (bb < NB_REO + NB_CONV + NB_PT) {
        // ---- P converts: PbT (transposed) and Pb
        int idx = (bb - NB_REO - NB_CONV)*256 + tid;
        if (idx < EMB_*RANK_) {
            int k = idx >> 7, c = idx & 127;
            g_PbT[k*RANK_ + c] = __float2bfloat16_rn(P[c*EMB_ + k]);
        } else {
            int j = idx - EMB_*RANK_;
            g_Pb[j] = __float2bfloat16_rn(P[j]);
        }
    } else {
        // ---- state init
        int i = (bb - NB_REO - NB_CONV - NB_PT)*256 + tid;   // 0..32767
        if (i < B_*H_) {
            int b = i >> 10, j = i & 1023;
            float h0v = enc_state[i];
            float h1v = enc_state[B_*H_ + i];
            g_c0[i] = 0.f; g_c1[i] = 0.f;
            __nv_bfloat16 h0b = __float2bfloat16_rn(h0v);
            __nv_bfloat16 h1b = __float2bfloat16_rn(h1v);
            g_xb[0][b*K1_ + j]        = h0b;
            g_xb[0][b*K1_ + 1024 + j] = h1b;
            g_xa[0][b*KL_ + 1024 + j] = h0b;
            g_xa[0][b*KL_ + j]        = __float2bfloat16_rn(0.f);   // ctx = 0
        }
        {
            __nv_bfloat162 z(__float2bfloat16_rn(0.f), __float2bfloat16_rn(0.f));
            *(__nv_bfloat162*)&g_featsB[(size_t)NROWS*2048 + i*2] = z;
        }
        if (i < NRPAD) g_sumexp[i] = 0.f;
        if (i == 0) { g_bar_count = 0; g_bar_gen = 0; out[0] = 0.f; }
    }
}

// ---------------- embedding via bf16 mma: 128x128 tiles ---------------------------
#define EMB_TS (128*136*2)      /* 34816 */
#define SMEM_EMB (2*EMB_TS)

__global__ void __launch_bounds__(256) embed_mma(const int* __restrict__ tok) {
    extern __shared__ __align__(16) char msm[];
    typedef __nv_bfloat16 TT[128][136];
    TT* ts = (TT*)msm;
    TT* ps = (TT*)(msm + EMB_TS);
    int tid = threadIdx.x, lane = tid & 31, w = tid >> 5;
    int cbase = blockIdx.x * 128;
    int rbase = blockIdx.y * 128;
    #pragma unroll
    for (int q = 0; q < 8; q++) {
        int c = tid + q*256;
        int row = c >> 4, kc = c & 15;
        int r = rbase + row;
        int t = r >> 5, b = r & 31;
        int token = (t < TM1) ? tok[b*T_ + t] : 0;
        cp16(&(*ts)[row][kc*8], g_Eb + (size_t)token*RANK_ + kc*8);
        cp16(&(*ps)[row][kc*8], g_Pb + (size_t)row*EMB_ + cbase + kc*8);
    }
    cp_commit();
    cp_waitall();
    __syncthreads();
    int m0 = (w & 3)*32, n0 = (w >> 2)*64;
    float acc[2][8][4] = {};
    #pragma unroll
    for (int ks = 0; ks < 8; ks++) {
        uint32_t a0[4], a1[4];
        ldsm_x4(a0, &(*ts)[m0 + (lane & 15)][ks*16 + (lane >> 4)*8]);
        ldsm_x4(a1, &(*ts)[m0 + 16 + (lane & 15)][ks*16 + (lane >> 4)*8]);
        #pragma unroll
        for (int nb = 0; nb < 4; nb++) {
            uint32_t b[4];
            ldsm_x4_t(b, &(*ps)[ks*16 + (lane & 15)][n0 + nb*16 + (lane >> 4)*8]);
            mma_bf16(acc[0][nb*2],   a0, b[0], b[1]);
            mma_bf16(acc[0][nb*2+1], a0, b[2], b[3]);
            mma_bf16(acc[1][nb*2],   a1, b[0], b[1]);
            mma_bf16(acc[1][nb*2+1], a1, b[2], b[3]);
        }
    }
    #pragma unroll
    for (int mt = 0; mt < 2; mt++)
        #pragma unroll
        for (int j = 0; j < 8; j++) {
            int col = cbase + n0 + j*8 + 2*(lane & 3);
            int r = rbase + m0 + mt*16 + (lane >> 2);
            __nv_bfloat162 o0(__float2bfloat16_rn(acc[mt][j][0]), __float2bfloat16_rn(acc[mt][j][1]));
            __nv_bfloat162 o1(__float2bfloat16_rn(acc[mt][j][2]), __float2bfloat16_rn(acc[mt][j][3]));
            *(__nv_bfloat162*)&g_embB[(size_t)r*EMB_ + col]     = o0;
            *(__nv_bfloat162*)&g_embB[(size_t)(r+8)*EMB_ + col] = o1;
        }
}

// ---------------- embW = embB @ W0b[0:512] (fp32 out), 128x128 tiles, 3-stage ------
#define EMBW_XS (3*128*72*2)    /* 55296 */
#define EMBW_WS (3*64*136*2)    /* 52224 */
#define SMEM_EMBW (EMBW_XS + EMBW_WS)

__global__ void __launch_bounds__(256) embw_mma() {
    extern __shared__ __align__(16) char esm[];
    typedef __nv_bfloat16 XT[128][72];
    typedef __nv_bfloat16 WT[64][136];
    XT* xs = (XT*)esm;
    WT* ws = (WT*)(esm + EMBW_XS);
    int tid = threadIdx.x, lane = tid & 31, w = tid >> 5;
    int cbase = blockIdx.x * 128;
    int rbase = blockIdx.y * 128;
    int m0 = (w & 3) * 32, n0 = (w >> 2) * 64;
    float acc[2][8][4] = {};

    auto load_chunk = [&](int ch) {
        int st = ch % 3; int kb = ch * 64;
        #pragma unroll
        for (int q = 0; q < 4; q++) {
            int c = tid + q*256;
            int row = c >> 3, kc = c & 7;
            cp16(&xs[st][row][kc*8], g_embB + (size_t)(rbase + row)*EMB_ + kb + kc*8);
        }
        #pragma unroll
        for (int q = 0; q < 4; q++) {
            int c = tid + q*256;
            int kr = c >> 4, cc = c & 15;
            cp16(&ws[st][kr][cc*8], g_W0b + (size_t)(kb + kr)*G4 + cbase + cc*8);
        }
    };
    load_chunk(0); cp_commit();
    load_chunk(1); cp_commit();
    for (int ch = 0; ch < 8; ch++) {
        asm volatile("cp.async.wait_group 1;");
        __syncthreads();
        if (ch + 2 < 8) load_chunk(ch + 2);
        cp_commit();
        int st = ch % 3;
        #pragma unroll
        for (int ks = 0; ks < 4; ks++) {
            uint32_t a0[4], a1[4];
            ldsm_x4(a0, &xs[st][m0 + (lane & 15)][ks*16 + (lane >> 4)*8]);
            ldsm_x4(a1, &xs[st][m0 + 16 + (lane & 15)][ks*16 + (lane >> 4)*8]);
            #pragma unroll
            for (int nb = 0; nb < 4; nb++) {
                uint32_t b[4];
                ldsm_x4_t(b, &ws[st][ks*16 + (lane & 15)][n0 + nb*16 + (lane >> 4)*8]);
                mma_bf16(acc[0][nb*2],   a0, b[0], b[1]);
                mma_bf16(acc[0][nb*2+1], a0, b[2], b[3]);
                mma_bf16(acc[1][nb*2],   a1, b[0], b[1]);
                mma_bf16(acc[1][nb*2+1], a1, b[2], b[3]);
            }
        }
        __syncthreads();
    }
    #pragma unroll
    for (int mt = 0; mt < 2; mt++)
        #pragma unroll
        for (int j = 0; j < 8; j++) {
            int col = cbase + n0 + j*8 + 2*(lane & 3);
            int r = rbase + m0 + mt*16 + (lane >> 2);
            *(float2*)&g_embW[(size_t)r*G4 + col]     = make_float2(acc[mt][j][0], acc[mt][j][1]);
            *(float2*)&g_embW[(size_t)(r+8)*G4 + col] = make_float2(acc[mt][j][2], acc[mt][j][3]);
        }
}

// ================= persistent step loop (R8/R13 structure — best) ==================
#define XS_BYTES (4*32*72*2)
#define WS_BYTES (4*64*72*2)
#define SMEM_STEP (XS_BYTES + WS_BYTES)

// gates GEMM (K=2048, k-split 4, chunks of 64, depth-3 pipeline)
template<int WHICH>
__device__ void gates_phase(char* sraw, int bid, int p) {
    constexpr int NCH = 8;
    typedef __nv_bfloat16 XsT[32][72];
    typedef __nv_bfloat16 WsT[64][72];
    XsT* xs = (XsT*)sraw;
    WsT* ws = (WsT*)(sraw + XS_BYTES);
    const __nv_bfloat16* __restrict__ X = WHICH ? g_xb[p] : g_xa[p];
    const __nv_bfloat16* __restrict__ W = WHICH ? g_W1b : (g_W0b + (size_t)512*G4);
    int tid = threadIdx.x, lane = tid & 31, w = tid >> 5;
    int ctile  = bid & 63;
    int ksplit = bid >> 6;
    int cbase  = ctile * 64;
    int kstart = ksplit * 512;
    int n0 = w * 16;
    float acc[2][2][4] = {};

    auto load_chunk = [&](int ch) {
        int st = ch & 3; int kb = kstart + ch*64;
        #pragma unroll
        for (int q = 0; q < 2; q++) {
            int c = tid*2 + q;
            int row = c >> 3, kc = c & 7;
            cp16(&xs[st][row][kc*8], X + row*KL_ + kb + kc*8);
        }
        #pragma unroll
        for (int q = 0; q < 4; q++) {
            int c = tid + q*128;
            int row = c >> 3, cc = c & 7;
            cp16(&ws[st][row][cc*8], W + (size_t)(kb + row)*G4 + cbase + cc*8);
        }
    };
    load_chunk(0); cp_commit();
    load_chunk(1); cp_commit();
    load_chunk(2); cp_commit();
    for (int ch = 0; ch < NCH; ch++) {
        cp_wait2();
        __syncthreads();
        if (ch + 3 < NCH) load_chunk(ch + 3);
        cp_commit();
        int st = ch & 3;
        #pragma unroll
        for (int ks = 0; ks < 4; ks++) {
            uint32_t a0[4], a1[4], b[4];
            ldsm_x4(a0, &xs[st][(lane & 15)][ks*16 + (lane >> 4)*8]);
            ldsm_x4(a1, &xs[st][16 + (lane & 15)][ks*16 + (lane >> 4)*8]);
            ldsm_x4_t(b, &ws[st][ks*16 + (lane & 15)][n0 + (lane >> 4)*8]);
            mma_bf16(acc[0][0], a0, b[0], b[1]);
            mma_bf16(acc[0][1], a0, b[2], b[3]);
            mma_bf16(acc[1][0], a1, b[0], b[1]);
            mma_bf16(acc[1][1], a1, b[2], b[3]);
        }
    }
    cp_waitall();
    float* gp = g_gates_part[ksplit];
    #pragma unroll
    for (int mt = 0; mt < 2; mt++)
        #pragma unroll
        for (int nt = 0; nt < 2; nt++) {
            int row = mt*16 + (lane >> 2);
            int col = cbase + n0 + nt*8 + 2*(lane & 3);
            *(float2*)&gp[(size_t)row*G4 + col]     = make_float2(acc[mt][nt][0], acc[mt][nt][1]);
            *(float2*)&gp[(size_t)(row+8)*G4 + col] = make_float2(acc[mt][nt][2], acc[mt][nt][3]);
        }
}

// cell0: 256 blocks, each (b = bid&31, 128-unit slice)
__device__ void cell0_phase(int bid, int t, int p, const float* __restrict__ bias) {
    int b  = bid & 31;
    int u  = (bid >> 5)*128 + threadIdx.x;
    float4 ev = *(const float4*)&g_embW[((size_t)(t*B_ + b))*G4 + 4*u];
    float gi = bias[u]        + ev.x;
    float gf = bias[1024 + u] + ev.y;
    float gg = bias[2048 + u] + ev.z;
    float go = bias[3072 + u] + ev.w;
    #pragma unroll
    for (int pt = 0; pt < NSPLIT; pt++) {
        float4 gv = __ldcg((const float4*)&g_gates_part[pt][(size_t)b*G4 + 4*u]);
        gi += gv.x; gf += gv.y; gg += gv.z; go += gv.w;
    }
    float c = g_c0[b*H_ + u];
    float cn = sigf(gf)*c + sigf(gi)*tanhfast(gg);
    float hn = sigf(go)*tanhfast(cn);
    g_c0[b*H_ + u] = cn;
    __nv_bfloat16 hb = __float2bfloat16_rn(hn);
    g_xb[p][b*K1_ + u] = hb;                 // gates1 input this step
    g_xa[1-p][b*KL_ + 1024 + u] = hb;        // h0 next step
}

// cell1 + partial attention scores: 256 blocks, (b = bid>>3, 128-unit slice)
__device__ void cell1_phase(float* hs, int bid, int t, int p,
                            const float* __restrict__ bias,
                            const int* __restrict__ enc_lens) {
    int b     = bid >> 3;
    int slice = bid & 7;
    int tid = threadIdx.x;
    {
        int u = slice*128 + tid;
        float gi = bias[u], gf = bias[1024+u], gg = bias[2048+u], go = bias[3072+u];
        #pragma unroll
        for (int pt = 0; pt < NSPLIT; pt++) {
            float4 gv = __ldcg((const float4*)&g_gates_part[pt][(size_t)b*G4 + 4*u]);
            gi += gv.x; gf += gv.y; gg += gv.z; go += gv.w;
        }
        float c = g_c1[b*H_ + u];
        float cn = sigf(gf)*c + sigf(gi)*tanhfast(gg);
        float hn = sigf(go)*tanhfast(cn);
        g_c1[b*H_ + u] = cn;
        __nv_bfloat16 hb = __float2bfloat16_rn(hn);
        g_xb[1-p][b*K1_ + 1024 + u] = hb;          // h1 next step
        g_featsB[(size_t)(t*B_ + b)*2048 + u] = hb;
        hs[tid] = hn;
    }
    __syncthreads();
    int w = tid >> 5, lane = tid & 31;
    int len = enc_lens[b];
    #pragma unroll
    for (int i = 0; i < 14; i++) {
        int s = w*14 + i;
        if (s < len) {
            const __nv_bfloat16* e = g_encB + ((size_t)(s*B_ + b) << 10) + slice*128;
            uint2 v = *(const uint2*)(e + lane*4);
            const __nv_bfloat162* p2 = (const __nv_bfloat162*)&v;
            float2 f0 = __bfloat1622float2(p2[0]);
            float2 f1 = __bfloat1622float2(p2[1]);
            float a = f0.x*hs[lane*4] + f0.y*hs[lane*4+1]
                    + f1.x*hs[lane*4+2] + f1.y*hs[lane*4+3];
            #pragma unroll
            for (int o = 16; o; o >>= 1) a += __shfl_xor_sync(0xffffffffu, a, o);
            if (lane == 0) g_spart[slice][b*64 + s] = a;
        }
    }
}

// attention finish: softmax + ctx, 256 blocks, (b = bid>>3, 128-col slice)
__device__ void attn_fin(float* sc, int bid, int t, int p,
                         const int* __restrict__ enc_lens) {
    int b  = bid >> 3;
    int c0 = (bid & 7)*128;
    int tid = threadIdx.x;
    int len = enc_lens[b];
    if (tid < 64) {
        float v = -1.0e30f;
        if (tid < len) {
            v = 0.f;
            #pragma unroll
            for (int k = 0; k < 8; k++) v += __ldcg(&g_spart[k][b*64 + tid]);
        }
        sc[tid] = v;
    }
    __syncthreads();
    if (tid < 32) {
        int lane = tid;
        float v0 = sc[lane];
        float v1 = (lane + 32 < S_) ? sc[lane + 32] : -1.0e30f;
        float m = fmaxf(v0, v1);
        #pragma unroll
        for (int o = 16; o; o >>= 1) m = fmaxf(m, __shfl_xor_sync(0xffffffffu, m, o));
        float e0 = __expf(v0 - m);
        float e1 = (lane + 32 < S_) ? __expf(v1 - m) : 0.f;
        float sum = e0 + e1;
        #pragma unroll
        for (int o = 16; o; o >>= 1) sum += __shfl_xor_sync(0xffffffffu, sum, o);
        sc[lane] = e0 / sum;
        if (lane + 32 < S_) sc[lane + 32] = e1 / sum;
    }
    __syncthreads();
    int col = c0 + tid;
    float a = 0.f;
    #pragma unroll 8
    for (int s = 0; s < S_; s++)
        a = fmaf(sc[s], __bfloat162float(g_encB[((size_t)(s*B_ + b) << 10) + col]), a);
    __nv_bfloat16 ab = __float2bfloat16_rn(a);
    g_featsB[(size_t)(t*B_ + b)*2048 + 1024 + col] = ab;
    g_xa[1-p][b*KL_ + col] = ab;              // ctx next step
}

__global__ void __launch_bounds__(128, 2) step_loop(const float* __restrict__ b0,
                                                    const float* __restrict__ b1,
                                                    const int* __restrict__ enc_lens) {
    extern __shared__ __align__(16) char sraw[];
    __shared__ float s_hs[128];
    __shared__ float s_sc[64];
    int bid = blockIdx.x;
    for (int t = 0; t < TM1; t++) {
        int p = t & 1;
        gates_phase<0>(sraw, bid, p);
        gsync();
        cell0_phase(bid, t, p, b0);
        gsync();
        gates_phase<1>(sraw, bid, p);
        gsync();
        cell1_phase(s_hs, bid, t, p, b1, enc_lens);
        gsync();
        attn_fin(s_sc, bid, t, p, enc_lens);
        gsync();
    }
}

// ---------------- hproj = tanh(featsB @ WoB + bo), 128x64 tiles, bf16 out ----------
#define HP_XS (3*128*72*2)    /* 55296 */
#define HP_WS (3*64*72*2)     /* 27648 */
#define SMEM_HP (HP_XS + HP_WS)

__global__ void __launch_bounds__(256) hproj_mma(const float* __restrict__ bo) {
    extern __shared__ __align__(16) char hsm[];
    typedef __nv_bfloat16 XT[128][72];
    typedef __nv_bfloat16 WT[64][72];
    XT* xs = (XT*)hsm;
    WT* ws = (WT*)(hsm + HP_XS);
    int tid = threadIdx.x, lane = tid & 31, w = tid >> 5;
    int cbase = blockIdx.x * 64;
    int rbase = blockIdx.y * 128;
    int m0 = (w & 3) * 32, n0 = (w >> 2) * 32;
    float acc[2][4][4] = {};

    auto load_chunk = [&](int ch) {
        int st = ch % 3; int kb = ch * 64;
        #pragma unroll
        for (int q = 0; q < 4; q++) {
            int c = tid + q*256;
            int row = c >> 3, kc = c & 7;
            cp16(&xs[st][row][kc*8], g_featsB + (size_t)(rbase + row)*2048 + kb + kc*8);
        }
        #pragma unroll
        for (int q = 0; q < 2; q++) {
            int c = tid + q*256;
            int kr = c >> 3, cc = c & 7;
            cp16(&ws[st][kr][cc*8], g_WoB + (size_t)(kb + kr)*EMB_ + cbase + cc*8);
        }
    };
    load_chunk(0); cp_commit();
    load_chunk(1); cp_commit();
    for (int ch = 0; ch < 32; ch++) {
        asm volatile("cp.async.wait_group 1;");
        __syncthreads();
        if (ch + 2 < 32) load_chunk(ch + 2);
        cp_commit();
        int st = ch % 3;
        #pragma unroll
        for (int ks = 0; ks < 4; ks++) {
            uint32_t a0[4], a1[4];
            ldsm_x4(a0, &xs[st][m0 + (lane & 15)][ks*16 + (lane >> 4)*8]);
            ldsm_x4(a1, &xs[st][m0 + 16 + (lane & 15)][ks*16 + (lane >> 4)*8]);
            #pragma unroll
            for (int nb = 0; nb < 2; nb++) {
                uint32_t b[4];
                ldsm_x4_t(b, &ws[st][ks*16 + (lane & 15)][n0 + nb*16 + (lane >> 4)*8]);
                mma_bf16(acc[0][nb*2],   a0, b[0], b[1]);
                mma_bf16(acc[0][nb*2+1], a0, b[2], b[3]);
                mma_bf16(acc[1][nb*2],   a1, b[0], b[1]);
                mma_bf16(acc[1][nb*2+1], a1, b[2], b[3]);
            }
        }
        __syncthreads();
    }
    #pragma unroll
    for (int mt = 0; mt < 2; mt++)
        #pragma unroll
        for (int j = 0; j < 4; j++) {
            int col = cbase + n0 + j*8 + 2*(lane & 3);
            float b0v = bo[col], b1v = bo[col+1];
            int r = rbase + m0 + mt*16 + (lane >> 2);
            __nv_bfloat162 o0(__float2bfloat16_rn(tanhf(acc[mt][j][0] + b0v)),
                              __float2bfloat16_rn(tanhf(acc[mt][j][1] + b1v)));
            __nv_bfloat162 o1(__float2bfloat16_rn(tanhf(acc[mt][j][2] + b0v)),
                              __float2bfloat16_rn(tanhf(acc[mt][j][3] + b1v)));
            *(__nv_bfloat162*)&g_hprojB[(size_t)r*EMB_ + col]     = o0;
            *(__nv_bfloat162*)&g_hprojB[(size_t)(r+8)*EMB_ + col] = o1;
        }
}

// ---------------- tmp = hprojB @ PbT (128x128 tiles, fp32+bf16 out) ----------------
#define TP_XS (3*128*72*2)    /* 55296 */
#define TP_WS (3*64*136*2)    /* 52224 */
#define SMEM_TP (TP_XS + TP_WS)

__global__ void __launch_bounds__(256) tmp_mma() {
    extern __shared__ __align__(16) char tsm[];
    typedef __nv_bfloat16 XT[128][72];
    typedef __nv_bfloat16 WT[64][136];
    XT* xs = (XT*)tsm;
    WT* ws = (WT*)(tsm + TP_XS);
    int tid = threadIdx.x, lane = tid & 31, w = tid >> 5;
    int rbase = blockIdx.x * 128;
    int m0 = (w & 3) * 32, n0 = (w >> 2) * 64;
    float acc[2][8][4] = {};

    auto load_chunk = [&](int ch) {
        int st = ch % 3; int kb = ch * 64;
        #pragma unroll
        for (int q = 0; q < 4; q++) {
            int c = tid + q*256;
            int row = c >> 3, kc = c & 7;
            cp16(&xs[st][row][kc*8], g_hprojB + (size_t)(rbase + row)*EMB_ + kb + kc*8);
        }
        #pragma unroll
        for (int q = 0; q < 4; q++) {
            int c = tid + q*256;
            int kr = c >> 4, cc = c & 15;
            cp16(&ws[st][kr][cc*8], g_PbT + (size_t)(kb + kr)*RANK_ + cc*8);
        }
    };
    load_chunk(0); cp_commit();
    load_chunk(1); cp_commit();
    for (int ch = 0; ch < 8; ch++) {
        asm volatile("cp.async.wait_group 1;");
        __syncthreads();
        if (ch + 2 < 8) load_chunk(ch + 2);
        cp_commit();
        int st = ch % 3;
        #pragma unroll
        for (int ks = 0; ks < 4; ks++) {
            uint32_t a0[4], a1[4];
            ldsm_x4(a0, &xs[st][m0 + (lane & 15)][ks*16 + (lane >> 4)*8]);
            ldsm_x4(a1, &xs[st][m0 + 16 + (lane & 15)][ks*16 + (lane >> 4)*8]);
            #pragma unroll
            for (int nb = 0; nb < 4; nb++) {
                uint32_t b[4];
                ldsm_x4_t(b, &ws[st][ks*16 + (lane & 15)][n0 + nb*16 + (lane >> 4)*8]);
                mma_bf16(acc[0][nb*2],   a0, b[0], b[1]);
                mma_bf16(acc[0][nb*2+1], a0, b[2], b[3]);
                mma_bf16(acc[1][nb*2],   a1, b[0], b[1]);
                mma_bf16(acc[1][nb*2+1], a1, b[2], b[3]);
            }
        }
        __syncthreads();
    }
    #pragma unroll
    for (int mt = 0; mt < 2; mt++)
        #pragma unroll
        for (int j = 0; j < 8; j++) {
            int col = n0 + j*8 + 2*(lane & 3);
            int r = rbase + m0 + mt*16 + (lane >> 2);
            *(float2*)&g_tmp[(size_t)r*RANK_ + col]     = make_float2(acc[mt][j][0], acc[mt][j][1]);
            *(float2*)&g_tmp[(size_t)(r+8)*RANK_ + col] = make_float2(acc[mt][j][2], acc[mt][j][3]);
            __nv_bfloat162 t0(__float2bfloat16_rn(acc[mt][j][0]), __float2bfloat16_rn(acc[mt][j][1]));
            __nv_bfloat162 t1(__float2bfloat16_rn(acc[mt][j][2]), __float2bfloat16_rn(acc[mt][j][3]));
            *(__nv_bfloat162*)&g_tmpB[(size_t)r*RANK_ + col]     = t0;
            *(__nv_bfloat162*)&g_tmpB[(size_t)(r+8)*RANK_ + col] = t1;
        }
}

// ---------------- sumexp via bf16 mma: 128 rows x 128 vocab per block ----------------
#define SE_TS (128*136*2)       /* 34816 */
#define SMEM_SE (2*SE_TS)

__global__ void __launch_bounds__(256) sumexp_mma() {
    extern __shared__ __align__(16) char ssm[];
    typedef __nv_bfloat16 TT[128][136];
    TT* ts = (TT*)ssm;
    TT* es = (TT*)(ssm + SE_TS);
    int tid = threadIdx.x, lane = tid & 31, w = tid >> 5;
    int vbase = blockIdx.x * 128, rbase = blockIdx.y * 128;
    #pragma unroll
    for (int q = 0; q < 8; q++) {
        int c = tid + q*256;
        int row = c >> 4, kc = c & 15;
        *(uint4*)&(*ts)[row][kc*8] = *(const uint4*)&g_tmpB[(size_t)(rbase + row)*RANK_ + kc*8];
        *(uint4*)&(*es)[row][kc*8] = *(const uint4*)&g_Eb[(size_t)(vbase + row)*RANK_ + kc*8];
    }
    __syncthreads();
    int m0 = (w & 3)*32, n0 = (w >> 2)*64;
    float acc[2][8][4] = {};
    #pragma unroll
    for (int ks = 0; ks < 8; ks++) {
        uint32_t a0[4], a1[4];
        ldsm_x4(a0, &(*ts)[m0 + (lane & 15)][ks*16 + (lane >> 4)*8]);
        ldsm_x4(a1, &(*ts)[m0 + 16 + (lane & 15)][ks*16 + (lane >> 4)*8]);
        #pragma unroll
        for (int nb = 0; nb < 4; nb++) {
            uint32_t b[4];
            ldsm_x4(b, &(*es)[n0 + nb*16 + (lane & 15)][ks*16 + (lane >> 4)*8]);
            mma_bf16(acc[0][nb*2],   a0, b[0], b[2]);
            mma_bf16(acc[0][nb*2+1], a0, b[1], b[3]);
            mma_bf16(acc[1][nb*2],   a1, b[0], b[2]);
            mma_bf16(acc[1][nb*2+1], a1, b[1], b[3]);
        }
    }
    #pragma unroll
    for (int mt = 0; mt < 2; mt++) {
        float sA = 0.f, sB = 0.f;
        #pragma unroll
        for (int j = 0; j < 8; j++) {
            sA += fexp(acc[mt][j][0]) + fexp(acc[mt][j][1]);
            sB += fexp(acc[mt][j][2]) + fexp(acc[mt][j][3]);
        }
        sA += __shfl_xor_sync(0xffffffffu, sA, 1);
        sA += __shfl_xor_sync(0xffffffffu, sA, 2);
        sB += __shfl_xor_sync(0xffffffffu, sB, 1);
        sB += __shfl_xor_sync(0xffffffffu, sB, 2);
        if ((lane & 3) == 0) {
            int row = rbase + m0 + mt*16 + (lane >> 2);
            atomicAdd(&g_sumexp[row], sA);
            atomicAdd(&g_sumexp[row + 8], sB);
        }
    }
}

// ---------------- label logit + loss (merged; runs after sumexp) -----------------------
__global__ void label_loss_kernel(const int* __restrict__ tok, const float* __restrict__ E,
                                  const int* __restrict__ tgt_lens, float* out) {
    int r = blockIdx.x*8 + (threadIdx.x >> 5);
    if (r >= NROWS) return;
    int lane = threadIdx.x & 31;
    int t = r / B_, b = r % B_;
    int lbl = tok[b*T_ + t + 1];
    float a = 0.f;
    for (int e = lane; e < RANK_; e += 32)
        a += g_tmp[(size_t)r*RANK_ + e] * E[(size_t)lbl*RANK_ + e];
    #pragma unroll
    for (int o = 16; o; o >>= 1) a += __shfl_xor_sync(0xffffffffu, a, o);
    if (lane == 0 && t < tgt_lens[b] - 1) {
        float nll = logf(g_sumexp[r]) - a;
        atomicAdd(out, nll);
    }
}

// ---------------- launch ----------------------------------------------------------------
extern "C" void kernel_launch(void* const* d_in, const int* in_sizes, int n_in,
                              void* d_out, int out_size) {
    const float* encoded   = (const float*)d_in[0];
    const float* enc_state = (const float*)d_in[1];
    const int*   tok       = (const int*)  d_in[2];
    const int*   enc_lens  = (const int*)  d_in[3];
    const int*   tgt_lens  = (const int*)  d_in[4];
    const float* E         = (const float*)d_in[5];
    const float* P         = (const float*)d_in[6];
    const float* W0        = (const float*)d_in[7];
    const float* U0        = (const float*)d_in[8];
    const float* b0        = (const float*)d_in[9];
    const float* W1        = (const float*)d_in[10];
    const float* U1        = (const float*)d_in[11];
    const float* b1        = (const float*)d_in[12];
    const float* Wo        = (const float*)d_in[13];
    const float* bo        = (const float*)d_in[14];
    float* out = (float*)d_out;

    static int s_attr_done = 0;
    if (!s_attr_done) {
        cudaFuncSetAttribute(step_loop,  cudaFuncAttributeMaxDynamicSharedMemorySize, SMEM_STEP);
        cudaFuncSetAttribute(embed_mma,  cudaFuncAttributeMaxDynamicSharedMemorySize, SMEM_EMB);
        cudaFuncSetAttribute(embw_mma,   cudaFuncAttributeMaxDynamicSharedMemorySize, SMEM_EMBW);
        cudaFuncSetAttribute(hproj_mma,  cudaFuncAttributeMaxDynamicSharedMemorySize, SMEM_HP);
        cudaFuncSetAttribute(tmp_mma,    cudaFuncAttributeMaxDynamicSharedMemorySize, SMEM_TP);
        cudaFuncSetAttribute(sumexp_mma, cudaFuncAttributeMaxDynamicSharedMemorySize, SMEM_SE);
        s_attr_done = 1;
    }

    mega_setup<<<NB_SETUP, 256>>>(W0, U0, W1, U1, E, Wo, encoded, P, enc_state, out);
    embed_mma<<<dim3(4, 12), 256, SMEM_EMB>>>(tok);
    embw_mma<<<dim3(32, 12), 256, SMEM_EMBW>>>();

    step_loop<<<NBLK, 128, SMEM_STEP>>>(b0, b1, enc_lens);

    hproj_mma<<<dim3(8, 12), 256, SMEM_HP>>>(bo);
    tmp_mma<<<12, 256, SMEM_TP>>>();
    sumexp_mma<<<dim3(250, 12), 256, SMEM_SE>>>();
    label_loss_kernel<<<188, 256>>>(tok, E, tgt_lens, out);
}